// round 9
// baseline (speedup 1.0000x reference)
#include <cuda_runtime.h>
#include <cuda_bf16.h>
#include <cstdint>

// ---------------- problem constants ----------------
#define BB     4
#define CC     64
#define H0     48
#define W0     48
#define QQ     16384
#define MROWS  (BB*QQ*4)     // 262144
#define HID    256
#define K0P    272           // layer-0 K (260) padded to multiple of 8

// ---------------- scratch ----------------
__device__ float g_feat [BB*CC*H0*W0];
__device__ float g_feat1[BB*CC*96*96];
__device__ float g_feat2[BB*CC*192*192];
__device__ float g_feat3[BB*CC*384*384];
__device__ float g_feat4[BB*CC*192*192];
__device__ float g_feat5[BB*CC*96*96];
__device__ float g_X  [(size_t)MROWS*K0P];
__device__ float g_H0b[(size_t)MROWS*HID];
__device__ float g_H1b[(size_t)MROWS*HID];
__device__ float g_Wt [256*K0P + 3*256*256];   // transposed weights [n][k]
__device__ float g_P  [(size_t)MROWS*3];
__device__ float g_area[MROWS];

// ================= enc conv (tiny, unchanged) =================
__global__ void enc_conv(const float* __restrict__ inp,
                         const float* __restrict__ w,
                         const float* __restrict__ b)
{
    int idx = blockIdx.x*256 + threadIdx.x;
    if (idx >= BB*CC*H0*W0) return;
    int x  = idx % W0;
    int y  = (idx / W0) % H0;
    int co = (idx / (H0*W0)) % CC;
    int bb = idx / (H0*W0*CC);
    float acc = b[co];
    const float* ib = inp + (size_t)bb*3*H0*W0;
    #pragma unroll
    for (int ci = 0; ci < 3; ci++) {
        #pragma unroll
        for (int ky = 0; ky < 3; ky++) {
            int yy = y + ky - 1;
            if (yy < 0 || yy >= H0) continue;
            #pragma unroll
            for (int kx = 0; kx < 3; kx++) {
                int xx = x + kx - 1;
                if (xx < 0 || xx >= W0) continue;
                acc += ib[ci*H0*W0 + yy*W0 + xx] * w[(co*3 + ci)*9 + ky*3 + kx];
            }
        }
    }
    g_feat[idx] = acc;
}

// ================= up conv 3x3 (64->256) + pixel shuffle, 16 outch/block =================
// grid (ceil(W/32), ceil(H/32), B*16), block 128. 2x4 px/thread, 16 channels.
__global__ void __launch_bounds__(128)
up_conv_ps4(const float* __restrict__ in, float* __restrict__ out,
            int H, int W,
            const float* __restrict__ w, const float* __restrict__ bias)
{
    __shared__ float s_in[4][34][36];     // rows padded to 36 floats -> 19.6 KB
    __shared__ float s_w[4][16][12];      // per-chunk weights        -> 3 KB
    int tid = threadIdx.x;
    int tx = tid & 7, ty = tid >> 3;
    int x0 = blockIdx.x*32, y0 = blockIdx.y*32;
    int bb = blockIdx.z >> 4;
    int base16 = (blockIdx.z & 15)*16;    // first of 16 raw conv out-channels
    const float* inb = in + (size_t)bb*CC*H*W;
    int bxp = x0 + tx*4;
    int byp = y0 + ty*2;

    float acc[16][8];
    #pragma unroll
    for (int f = 0; f < 16; f++)
        #pragma unroll
        for (int p = 0; p < 8; p++) acc[f][p] = 0.f;

    for (int c0 = 0; c0 < CC; c0 += 4) {
        __syncthreads();
        // input tile 4ci x 34 x 34
        for (int i = tid; i < 4*1156; i += 128) {
            int ci = i / 1156, rem = i % 1156;
            int r = rem / 34, c = rem % 34;
            int y = y0 + r - 1, x = x0 + c - 1;
            float v = 0.f;
            if (y >= 0 && y < H && x >= 0 && x < W)
                v = inb[(size_t)(c0+ci)*H*W + y*W + x];
            s_in[ci][r][c] = v;
        }
        // weights for this chunk: 4ci x 16 filters x 9
        for (int i = tid; i < 576; i += 128) {
            int ci = i / 144, rem = i % 144;
            int f = rem / 9, k = rem % 9;
            s_w[ci][f][k] = w[((size_t)(base16 + f)*CC + c0+ci)*9 + k];
        }
        __syncthreads();
        #pragma unroll
        for (int ci = 0; ci < 4; ci++) {
            float v[4][8];
            #pragma unroll
            for (int r = 0; r < 4; r++) {
                float4 p0 = *(const float4*)&s_in[ci][ty*2 + r][tx*4];
                float4 p1 = *(const float4*)&s_in[ci][ty*2 + r][tx*4 + 4];
                v[r][0] = p0.x; v[r][1] = p0.y; v[r][2] = p0.z; v[r][3] = p0.w;
                v[r][4] = p1.x; v[r][5] = p1.y; v[r][6] = p1.z; v[r][7] = p1.w;
            }
            #pragma unroll
            for (int f = 0; f < 16; f++) {
                float4 w0 = *(const float4*)&s_w[ci][f][0];
                float4 w1 = *(const float4*)&s_w[ci][f][4];
                float4 w2 = *(const float4*)&s_w[ci][f][8];
                float wr[9] = {w0.x, w0.y, w0.z, w0.w, w1.x, w1.y, w1.z, w1.w, w2.x};
                #pragma unroll
                for (int py = 0; py < 2; py++)
                    #pragma unroll
                    for (int px = 0; px < 4; px++) {
                        float a = acc[f][py*4 + px];
                        #pragma unroll
                        for (int ky = 0; ky < 3; ky++)
                            #pragma unroll
                            for (int kx = 0; kx < 3; kx++)
                                a += v[py+ky][px+kx] * wr[ky*3+kx];
                        acc[f][py*4 + px] = a;
                    }
            }
        }
    }

    if (bxp < W) {
        int H2 = 2*H, W2 = 2*W;
        #pragma unroll
        for (int lg = 0; lg < 4; lg++) {
            int cog = (base16 >> 2) + lg;             // shuffle group index
            float b4[4];
            #pragma unroll
            for (int c = 0; c < 4; c++) b4[c] = bias[base16 + lg*4 + c];
            float* ob = out + ((size_t)bb*CC + cog)*H2*W2;
            #pragma unroll
            for (int py = 0; py < 2; py++) {
                int yo = byp + py;
                if (yo >= H) continue;
                #pragma unroll
                for (int r = 0; r < 2; r++) {
                    float* orow = ob + (size_t)(2*yo + r)*W2 + 2*bxp;
                    int f0 = lg*4 + 2*r, f1 = lg*4 + 2*r + 1;
                    float4 q0 = make_float4(acc[f0][py*4+0] + b4[2*r+0],
                                            acc[f1][py*4+0] + b4[2*r+1],
                                            acc[f0][py*4+1] + b4[2*r+0],
                                            acc[f1][py*4+1] + b4[2*r+1]);
                    float4 q1 = make_float4(acc[f0][py*4+2] + b4[2*r+0],
                                            acc[f1][py*4+2] + b4[2*r+1],
                                            acc[f0][py*4+3] + b4[2*r+0],
                                            acc[f1][py*4+3] + b4[2*r+1]);
                    *(float4*)(orow)     = q0;
                    *(float4*)(orow + 4) = q1;
                }
            }
        }
    }
}

// ================= stride2 conv3x3 + 1x1 skip (unchanged, passing) =================
__global__ void down_fused(const float* __restrict__ in3, const float* __restrict__ skin,
                           float* __restrict__ out, int OH, int OW,
                           const float* __restrict__ dw, const float* __restrict__ db,
                           const float* __restrict__ sw, const float* __restrict__ sb)
{
    __shared__ float s_in[8][33][33];
    __shared__ float s_w[4][8][9];
    __shared__ float s_sw[4][8];
    int IH = 2*OH, IW = 2*OW;
    int tx = threadIdx.x, ty = threadIdx.y, tid = ty*16 + tx;
    int x0 = blockIdx.x*16, y0 = blockIdx.y*16;
    int bb = blockIdx.z >> 4;
    int cog = blockIdx.z & 15;
    float acc[4] = {0.f,0.f,0.f,0.f};
    const float* inb = in3 + (size_t)bb*CC*IH*IW;
    const float* skb = skin + (size_t)bb*CC*OH*OW;
    int oy = y0 + ty, ox = x0 + tx;

    for (int c0 = 0; c0 < CC; c0 += 8) {
        for (int i = tid; i < 8*33*33; i += 256) {
            int ci = i / 1089, rem = i % 1089, r = rem / 33, c = rem % 33;
            int y = 2*y0 - 1 + r, x = 2*x0 - 1 + c;
            float v = 0.f;
            if (y >= 0 && y < IH && x >= 0 && x < IW)
                v = inb[(size_t)(c0+ci)*IH*IW + y*IW + x];
            s_in[ci][r][c] = v;
        }
        for (int i = tid; i < 288; i += 256) {
            int col = i / 72, rem = i % 72, ci = rem / 9, k = rem % 9;
            s_w[col][ci][k] = dw[((size_t)(cog*4+col)*CC + c0+ci)*9 + k];
        }
        if (tid < 32) {
            int col = tid >> 3, ci = tid & 7;
            s_sw[col][ci] = sw[(cog*4+col)*CC + c0+ci];
        }
        __syncthreads();
        #pragma unroll
        for (int ci = 0; ci < 8; ci++) {
            float v[9];
            #pragma unroll
            for (int j = 0; j < 9; j++) v[j] = s_in[ci][2*ty + j/3][2*tx + j%3];
            float sv = skb[(size_t)(c0+ci)*OH*OW + oy*OW + ox];
            #pragma unroll
            for (int col = 0; col < 4; col++) {
                float a = acc[col];
                #pragma unroll
                for (int k = 0; k < 9; k++) a += v[k]*s_w[col][ci][k];
                a += sv * s_sw[col][ci];
                acc[col] = a;
            }
        }
        __syncthreads();
    }
    float* ob = out + (size_t)bb*CC*OH*OW;
    #pragma unroll
    for (int col = 0; col < 4; col++) {
        int co = cog*4 + col;
        ob[(size_t)co*OH*OW + oy*OW + ox] = acc[col] + db[co] + sb[co];
    }
}

// ================= weight prep: transpose (fp32) =================
__global__ void prep_wt(const float* __restrict__ w0, const float* __restrict__ w1,
                        const float* __restrict__ w2, const float* __restrict__ w3)
{
    int i = blockIdx.x*256 + threadIdx.x;
    int total = 256*K0P + 3*256*256;
    if (i >= total) return;
    float v;
    if (i < 256*K0P) {
        int n = i / K0P, k = i % K0P;
        v = (k < 260) ? w0[(size_t)k*256 + n] : 0.0f;
    } else {
        int j = i - 256*K0P;
        int l = j / 65536, r = j % 65536;
        int n = r / 256, k = r % 256;
        const float* ws = (l == 0) ? w1 : (l == 1) ? w2 : w3;
        v = ws[(size_t)k*256 + n];
    }
    g_Wt[i] = v;
}

// ================= gather + build X =================
__device__ __forceinline__ int nidx(float cc, float n)
{
    float f = rintf((cc + 1.0f)*(n*0.5f) - 0.5f);
    f = fminf(fmaxf(f, 0.0f), n - 1.0f);
    return (int)f;
}

__global__ void gather_build(const float* __restrict__ coord, const float* __restrict__ cell)
{
    int tid = threadIdx.x;
    int row = blockIdx.x*4 + (tid >> 6);
    int c   = tid & 63;
    int s   = row & 3;
    int bq  = row >> 2;
    int b   = bq >> 14;
    float cy = coord[(size_t)bq*2 + 0];
    float cx = coord[(size_t)bq*2 + 1];
    float vx = (s & 2) ? 1.f : -1.f;
    float vy = (s & 1) ? 1.f : -1.f;
    const float RX = 1.0f/48.0f;
    float sy = fminf(fmaxf(cy + vx*RX + 1e-6f, -1.f + 1e-6f), 1.f - 1e-6f);
    float sx = fminf(fmaxf(cx + vy*RX + 1e-6f, -1.f + 1e-6f), 1.f - 1e-6f);
    int iy0 = nidx(sy, 48.f),  ix0 = nidx(sx, 48.f);
    int iy1 = nidx(sy, 96.f),  ix1 = nidx(sx, 96.f);
    int iy2 = nidx(sy, 192.f), ix2 = nidx(sx, 192.f);
    int iy3 = nidx(sy, 384.f), ix3 = nidx(sx, 384.f);

    float* xr = g_X + (size_t)row*K0P;
    xr[c]       = g_feat [((size_t)(b*CC + c)*48  + iy0)*48  + ix0];
    xr[64 + c]  = g_feat5[((size_t)(b*CC + c)*96  + iy1)*96  + ix1];
    xr[128 + c] = g_feat4[((size_t)(b*CC + c)*192 + iy2)*192 + ix2];
    xr[192 + c] = g_feat3[((size_t)(b*CC + c)*384 + iy3)*384 + ix3];
    if (c == 0) {
        float qcy = -1.f + (2.f*iy0 + 1.f)/48.f;
        float qcx = -1.f + (2.f*ix0 + 1.f)/48.f;
        float ry_ = (cy - qcy)*48.f;
        float rx_ = (cx - qcx)*48.f;
        xr[256] = ry_;
        xr[257] = rx_;
        xr[258] = cell[(size_t)bq*2 + 0]*48.f;
        xr[259] = cell[(size_t)bq*2 + 1]*48.f;
        g_area[row] = fabsf(ry_*rx_) + 1e-9f;
    }
    if (c < 12) xr[260 + c] = 0.0f;   // pad to 272
}

// ================= scalar-FFMA SGEMM, 128x128 tile, 8x8/thread =================
__global__ void __launch_bounds__(256)
gemm_f32(const float* __restrict__ A, const float* __restrict__ Wt,
         const float* __restrict__ bias, float* __restrict__ C, int K)
{
    __shared__ float As[2][8][128];
    __shared__ float Bs[2][8][128];
    int tid = threadIdx.x;
    int tx = tid & 15, ty = tid >> 4;
    int m0 = blockIdx.y*128, n0 = blockIdx.x*128;
    int lrow = tid >> 1, lk = (tid & 1)*4;
    const float* ap = A  + (size_t)(m0 + lrow)*K + lk;
    const float* bp = Wt + (size_t)(n0 + lrow)*K + lk;
    int NK = K >> 3;

    float acc[8][8];
    #pragma unroll
    for (int i = 0; i < 8; i++)
        #pragma unroll
        for (int j = 0; j < 8; j++) acc[i][j] = 0.f;

    float4 av = *(const float4*)ap;
    float4 bv = *(const float4*)bp;

    for (int it = 0; it < NK; it++) {
        int buf = it & 1;
        As[buf][lk+0][lrow] = av.x;
        As[buf][lk+1][lrow] = av.y;
        As[buf][lk+2][lrow] = av.z;
        As[buf][lk+3][lrow] = av.w;
        Bs[buf][lk+0][lrow] = bv.x;
        Bs[buf][lk+1][lrow] = bv.y;
        Bs[buf][lk+2][lrow] = bv.z;
        Bs[buf][lk+3][lrow] = bv.w;
        if (it + 1 < NK) {
            av = *(const float4*)(ap + (it+1)*8);
            bv = *(const float4*)(bp + (it+1)*8);
        }
        __syncthreads();
        #pragma unroll
        for (int kk = 0; kk < 8; kk++) {
            float a[8], b[8];
            *(float4*)(a)   = *(const float4*)&As[buf][kk][ty*4];
            *(float4*)(a+4) = *(const float4*)&As[buf][kk][ty*4 + 64];
            *(float4*)(b)   = *(const float4*)&Bs[buf][kk][tx*4];
            *(float4*)(b+4) = *(const float4*)&Bs[buf][kk][tx*4 + 64];
            #pragma unroll
            for (int i = 0; i < 8; i++)
                #pragma unroll
                for (int j = 0; j < 8; j++)
                    acc[i][j] += a[i]*b[j];
        }
    }

    float bn[8];
    #pragma unroll
    for (int j = 0; j < 8; j++)
        bn[j] = bias[n0 + ((j < 4) ? tx*4 + j : 64 + tx*4 + j - 4)];
    #pragma unroll
    for (int i = 0; i < 8; i++) {
        int m = m0 + ((i < 4) ? ty*4 + i : 64 + ty*4 + i - 4);
        float* cr = C + (size_t)m*HID + n0;
        float4 q0 = make_float4(fmaxf(acc[i][0] + bn[0], 0.f),
                                fmaxf(acc[i][1] + bn[1], 0.f),
                                fmaxf(acc[i][2] + bn[2], 0.f),
                                fmaxf(acc[i][3] + bn[3], 0.f));
        float4 q1 = make_float4(fmaxf(acc[i][4] + bn[4], 0.f),
                                fmaxf(acc[i][5] + bn[5], 0.f),
                                fmaxf(acc[i][6] + bn[6], 0.f),
                                fmaxf(acc[i][7] + bn[7], 0.f));
        *(float4*)(cr + tx*4)      = q0;
        *(float4*)(cr + 64 + tx*4) = q1;
    }
}

// ================= last layer: [M,256]@[256,3]+b =================
__global__ void mlp_last(const float* __restrict__ Hin, const float* __restrict__ W4,
                         const float* __restrict__ b4)
{
    int warp = threadIdx.x >> 5, lane = threadIdx.x & 31;
    int row = blockIdx.x*4 + warp;
    const float* hr = Hin + (size_t)row*HID;
    float a0 = 0.f, a1 = 0.f, a2 = 0.f;
    for (int k = lane; k < HID; k += 32) {
        float h = hr[k];
        a0 += h*W4[k*3 + 0];
        a1 += h*W4[k*3 + 1];
        a2 += h*W4[k*3 + 2];
    }
    #pragma unroll
    for (int o = 16; o; o >>= 1) {
        a0 += __shfl_down_sync(0xffffffffu, a0, o);
        a1 += __shfl_down_sync(0xffffffffu, a1, o);
        a2 += __shfl_down_sync(0xffffffffu, a2, o);
    }
    if (lane == 0) {
        g_P[(size_t)row*3 + 0] = a0 + b4[0];
        g_P[(size_t)row*3 + 1] = a1 + b4[1];
        g_P[(size_t)row*3 + 2] = a2 + b4[2];
    }
}

// ================= ensemble + bilinear border skip =================
__global__ void ensemble(const float* __restrict__ coord, const float* __restrict__ inp,
                         float* __restrict__ out)
{
    int bq = blockIdx.x*256 + threadIdx.x;
    if (bq >= BB*QQ) return;
    int b = bq >> 14;
    float cy = coord[(size_t)bq*2 + 0];
    float cx = coord[(size_t)bq*2 + 1];
    int base = bq*4;
    float a0 = g_area[base+0], a1 = g_area[base+1], a2 = g_area[base+2], a3 = g_area[base+3];
    float inv = 1.0f/(a0 + a1 + a2 + a3);
    float w0 = a3*inv, w1 = a2*inv, w2 = a1*inv, w3 = a0*inv;
    float r[3];
    #pragma unroll
    for (int c = 0; c < 3; c++) {
        r[c] = g_P[(size_t)(base+0)*3 + c]*w0
             + g_P[(size_t)(base+1)*3 + c]*w1
             + g_P[(size_t)(base+2)*3 + c]*w2
             + g_P[(size_t)(base+3)*3 + c]*w3;
    }
    float fy = fminf(fmaxf((cy + 1.f)*24.f - 0.5f, 0.f), 47.f);
    float fx = fminf(fmaxf((cx + 1.f)*24.f - 0.5f, 0.f), 47.f);
    float y0f = floorf(fy), x0f = floorf(fx);
    int y0 = (int)y0f, x0 = (int)x0f;
    float wy = fy - y0f, wx = fx - x0f;
    int y1 = min(y0 + 1, 47), x1 = min(x0 + 1, 47);
    const float* ib = inp + (size_t)b*3*H0*W0;
    #pragma unroll
    for (int ch = 0; ch < 3; ch++) {
        const float* p = ib + ch*H0*W0;
        float v00 = p[y0*48 + x0], v01 = p[y0*48 + x1];
        float v10 = p[y1*48 + x0], v11 = p[y1*48 + x1];
        r[ch] += v00*(1.f - wy)*(1.f - wx) + v01*(1.f - wy)*wx
               + v10*wy*(1.f - wx) + v11*wy*wx;
        out[(size_t)bq*3 + ch] = r[ch];
    }
}

// ================= host launch =================
extern "C" void kernel_launch(void* const* d_in, const int* in_sizes, int n_in,
                              void* d_out, int out_size)
{
    const float* inp     = (const float*)d_in[0];
    const float* coord   = (const float*)d_in[1];
    const float* cell    = (const float*)d_in[2];
    const float* enc_w   = (const float*)d_in[3];
    const float* enc_b   = (const float*)d_in[4];
    const float* up1_w   = (const float*)d_in[5];
    const float* up1_b   = (const float*)d_in[6];
    const float* up2_w   = (const float*)d_in[7];
    const float* up2_b   = (const float*)d_in[8];
    const float* up3_w   = (const float*)d_in[9];
    const float* up3_b   = (const float*)d_in[10];
    const float* skip1_w = (const float*)d_in[11];
    const float* skip1_b = (const float*)d_in[12];
    const float* skip2_w = (const float*)d_in[13];
    const float* skip2_b = (const float*)d_in[14];
    const float* down4_w = (const float*)d_in[15];
    const float* down4_b = (const float*)d_in[16];
    const float* down5_w = (const float*)d_in[17];
    const float* down5_b = (const float*)d_in[18];
    const float* mlp_w0  = (const float*)d_in[19];
    const float* mlp_b0  = (const float*)d_in[20];
    const float* mlp_w1  = (const float*)d_in[21];
    const float* mlp_b1  = (const float*)d_in[22];
    const float* mlp_w2  = (const float*)d_in[23];
    const float* mlp_b2  = (const float*)d_in[24];
    const float* mlp_w3  = (const float*)d_in[25];
    const float* mlp_b3  = (const float*)d_in[26];
    const float* mlp_w4  = (const float*)d_in[27];
    const float* mlp_b4  = (const float*)d_in[28];
    float* out = (float*)d_out;

    float *p_feat, *p_feat1, *p_feat2, *p_feat3, *p_feat4, *p_feat5;
    float *p_X, *p_H0, *p_H1, *p_Wt;
    cudaGetSymbolAddress((void**)&p_feat,  g_feat);
    cudaGetSymbolAddress((void**)&p_feat1, g_feat1);
    cudaGetSymbolAddress((void**)&p_feat2, g_feat2);
    cudaGetSymbolAddress((void**)&p_feat3, g_feat3);
    cudaGetSymbolAddress((void**)&p_feat4, g_feat4);
    cudaGetSymbolAddress((void**)&p_feat5, g_feat5);
    cudaGetSymbolAddress((void**)&p_X,  g_X);
    cudaGetSymbolAddress((void**)&p_H0, g_H0b);
    cudaGetSymbolAddress((void**)&p_H1, g_H1b);
    cudaGetSymbolAddress((void**)&p_Wt, g_Wt);

    // weight prep (independent of convs)
    {
        int total = 256*K0P + 3*256*256;
        prep_wt<<<(total + 255)/256, 256>>>(mlp_w0, mlp_w1, mlp_w2, mlp_w3);
    }
    // encoder + pyramid
    {
        int total = BB*CC*H0*W0;
        enc_conv<<<(total + 255)/256, 256>>>(inp, enc_w, enc_b);
        up_conv_ps4<<<dim3(2, 2, BB*16), 128>>>(p_feat,  p_feat1, 48, 48,  up1_w, up1_b);
        up_conv_ps4<<<dim3(3, 3, BB*16), 128>>>(p_feat1, p_feat2, 96, 96,  up2_w, up2_b);
        up_conv_ps4<<<dim3(6, 6, BB*16), 128>>>(p_feat2, p_feat3, 192,192, up3_w, up3_b);
        dim3 blk(16,16);
        down_fused<<<dim3(12, 12, BB*16), blk>>>(p_feat3, p_feat2, p_feat4, 192, 192,
                                                 down4_w, down4_b, skip1_w, skip1_b);
        down_fused<<<dim3(6,  6,  BB*16), blk>>>(p_feat4, p_feat1, p_feat5, 96, 96,
                                                 down5_w, down5_b, skip2_w, skip2_b);
    }
    // gather + build X (fp32, padded to 272)
    gather_build<<<MROWS/4, 256>>>(coord, cell);

    // MLP hidden layers: scalar-FFMA 128x128 GEMM
    {
        dim3 grid(HID/128, MROWS/128);   // (2, 2048)
        const float* W1 = p_Wt + 256*K0P;
        const float* W2 = W1 + 65536;
        const float* W3 = W2 + 65536;
        gemm_f32<<<grid, 256>>>(p_X,  p_Wt, mlp_b0, p_H0, K0P);
        gemm_f32<<<grid, 256>>>(p_H0, W1,   mlp_b1, p_H1, 256);
        gemm_f32<<<grid, 256>>>(p_H1, W2,   mlp_b2, p_H0, 256);
        gemm_f32<<<grid, 256>>>(p_H0, W3,   mlp_b3, p_H1, 256);
    }
    // last layer + ensemble
    mlp_last<<<MROWS/4, 128>>>(p_H1, mlp_w4, mlp_b4);
    ensemble<<<(BB*QQ + 255)/256, 256>>>(coord, inp, out);
}

// round 10
// speedup vs baseline: 1.7718x; 1.7718x over previous
#include <cuda_runtime.h>
#include <cuda_bf16.h>
#include <cstdint>

// ---------------- problem constants ----------------
#define BB     4
#define CC     64
#define H0     48
#define W0     48
#define QQ     16384
#define MROWS  (BB*QQ*4)     // 262144
#define HID    256
#define K0P    272           // layer-0 K (260) padded to multiple of 8

// ---------------- scratch ----------------
__device__ float g_feat [BB*CC*H0*W0];
__device__ float g_feat1[BB*CC*96*96];
__device__ float g_feat2[BB*CC*192*192];
__device__ float g_feat3[BB*CC*384*384];
__device__ float g_feat4[BB*CC*192*192];
__device__ float g_feat5[BB*CC*96*96];
// channel-last copies for coalesced gather
__device__ float g_featL [BB*48*48*CC];
__device__ float g_feat5L[BB*96*96*CC];
__device__ float g_feat4L[BB*192*192*CC];
__device__ float g_feat3L[BB*384*384*CC];
__device__ float g_X  [(size_t)MROWS*K0P];
__device__ float g_H0b[(size_t)MROWS*HID];
__device__ float g_H1b[(size_t)MROWS*HID];
__device__ float g_Wt [256*K0P + 3*256*256];   // transposed weights [n][k]
__device__ float g_P  [(size_t)MROWS*3];
__device__ float g_area[MROWS];

// ================= enc conv (tiny, unchanged) =================
__global__ void enc_conv(const float* __restrict__ inp,
                         const float* __restrict__ w,
                         const float* __restrict__ b)
{
    int idx = blockIdx.x*256 + threadIdx.x;
    if (idx >= BB*CC*H0*W0) return;
    int x  = idx % W0;
    int y  = (idx / W0) % H0;
    int co = (idx / (H0*W0)) % CC;
    int bb = idx / (H0*W0*CC);
    float acc = b[co];
    const float* ib = inp + (size_t)bb*3*H0*W0;
    #pragma unroll
    for (int ci = 0; ci < 3; ci++) {
        #pragma unroll
        for (int ky = 0; ky < 3; ky++) {
            int yy = y + ky - 1;
            if (yy < 0 || yy >= H0) continue;
            #pragma unroll
            for (int kx = 0; kx < 3; kx++) {
                int xx = x + kx - 1;
                if (xx < 0 || xx >= W0) continue;
                acc += ib[ci*H0*W0 + yy*W0 + xx] * w[(co*3 + ci)*9 + ky*3 + kx];
            }
        }
    }
    g_feat[idx] = acc;
}

// ================= up conv 3x3 (64->256) + pixel shuffle, 4 outch/block =================
// grid (ceil(W/32), ceil(H/32), B*64), block 128. 2x4 px/thread.
// Vectorized task-based smem loader (aligned LDG.128 interior, guarded edges).
__global__ void __launch_bounds__(128)
up_conv_ps5(const float* __restrict__ in, float* __restrict__ out,
            int H, int W,
            const float* __restrict__ w, const float* __restrict__ bias)
{
    __shared__ float s_w[64][4][12];      // [ci][col][9 pad 12] -> 12.3 KB
    __shared__ float s_in[4][34][36];     // rows padded to 36    -> 19.6 KB
    int tid = threadIdx.x;
    int tx = tid & 7, ty = tid >> 3;
    int x0 = blockIdx.x*32, y0 = blockIdx.y*32;
    int bb = blockIdx.z >> 6;
    int cog = blockIdx.z & 63;
    const float* inb = in + (size_t)bb*CC*H*W;
    int bxp = x0 + tx*4;
    int byp = y0 + ty*2;

    // one-time weight preload
    for (int i = tid; i < 64*36; i += 128) {
        int ci = i / 36, rem = i % 36;
        int col = rem / 9, k = rem % 9;
        s_w[ci][col][k] = w[((size_t)(cog*4 + col)*CC + ci)*9 + k];
    }

    float acc[4][8];
    #pragma unroll
    for (int c = 0; c < 4; c++)
        #pragma unroll
        for (int p = 0; p < 8; p++) acc[c][p] = 0.f;

    for (int c0 = 0; c0 < CC; c0 += 4) {
        __syncthreads();
        // ---- vectorized loader: tasks = 4ci x 34row x 9seg (8 vec4 + 1 edge-pair) ----
        for (int idx = tid; idx < 1224; idx += 128) {
            int seg = idx % 9;
            int rc  = idx / 9;
            int r   = rc % 34;
            int ci  = rc / 34;
            int y = y0 + r - 1;
            bool yok = (y >= 0) && (y < H);
            const float* grow = inb + (size_t)(c0+ci)*H*W + (size_t)y*W;
            float* srow = &s_in[ci][r][0];
            if (seg < 8) {
                int x = x0 + seg*4;           // 16B-aligned global offset
                float4 v = make_float4(0.f, 0.f, 0.f, 0.f);
                if (yok) {
                    if (x + 3 < W) {
                        v = *(const float4*)(grow + x);
                    } else {
                        if (x + 0 < W) v.x = grow[x + 0];
                        if (x + 1 < W) v.y = grow[x + 1];
                        if (x + 2 < W) v.z = grow[x + 2];
                        if (x + 3 < W) v.w = grow[x + 3];
                    }
                }
                srow[1 + seg*4 + 0] = v.x;
                srow[1 + seg*4 + 1] = v.y;
                srow[1 + seg*4 + 2] = v.z;
                srow[1 + seg*4 + 3] = v.w;
            } else {
                float lft = 0.f, rgt = 0.f;
                if (yok) {
                    if (x0 > 0)       lft = grow[x0 - 1];
                    if (x0 + 32 < W)  rgt = grow[x0 + 32];
                }
                srow[0]  = lft;
                srow[33] = rgt;
            }
        }
        __syncthreads();
        #pragma unroll
        for (int ci = 0; ci < 4; ci++) {
            float v[4][8];
            #pragma unroll
            for (int r = 0; r < 4; r++) {
                float4 p0 = *(const float4*)&s_in[ci][ty*2 + r][tx*4];
                float4 p1 = *(const float4*)&s_in[ci][ty*2 + r][tx*4 + 4];
                v[r][0] = p0.x; v[r][1] = p0.y; v[r][2] = p0.z; v[r][3] = p0.w;
                v[r][4] = p1.x; v[r][5] = p1.y; v[r][6] = p1.z; v[r][7] = p1.w;
            }
            #pragma unroll
            for (int col = 0; col < 4; col++) {
                float4 w0 = *(const float4*)&s_w[c0+ci][col][0];
                float4 w1 = *(const float4*)&s_w[c0+ci][col][4];
                float4 w2 = *(const float4*)&s_w[c0+ci][col][8];
                float wr[9] = {w0.x, w0.y, w0.z, w0.w, w1.x, w1.y, w1.z, w1.w, w2.x};
                #pragma unroll
                for (int py = 0; py < 2; py++)
                    #pragma unroll
                    for (int px = 0; px < 4; px++) {
                        float a = acc[col][py*4 + px];
                        #pragma unroll
                        for (int ky = 0; ky < 3; ky++)
                            #pragma unroll
                            for (int kx = 0; kx < 3; kx++)
                                a += v[py+ky][px+kx] * wr[ky*3+kx];
                        acc[col][py*4 + px] = a;
                    }
            }
        }
    }

    if (bxp < W) {
        float b4[4];
        #pragma unroll
        for (int c = 0; c < 4; c++) b4[c] = bias[cog*4 + c];
        int H2 = 2*H, W2 = 2*W;
        float* ob = out + ((size_t)bb*CC + cog)*H2*W2;
        #pragma unroll
        for (int py = 0; py < 2; py++) {
            int yo = byp + py;
            if (yo >= H) continue;
            #pragma unroll
            for (int r = 0; r < 2; r++) {
                float* orow = ob + (size_t)(2*yo + r)*W2 + 2*bxp;
                float4 q0 = make_float4(acc[2*r+0][py*4+0] + b4[2*r+0],
                                        acc[2*r+1][py*4+0] + b4[2*r+1],
                                        acc[2*r+0][py*4+1] + b4[2*r+0],
                                        acc[2*r+1][py*4+1] + b4[2*r+1]);
                float4 q1 = make_float4(acc[2*r+0][py*4+2] + b4[2*r+0],
                                        acc[2*r+1][py*4+2] + b4[2*r+1],
                                        acc[2*r+0][py*4+3] + b4[2*r+0],
                                        acc[2*r+1][py*4+3] + b4[2*r+1]);
                *(float4*)(orow)     = q0;
                *(float4*)(orow + 4) = q1;
            }
        }
    }
}

// ================= stride2 conv3x3 + 1x1 skip (unchanged, passing) =================
__global__ void down_fused(const float* __restrict__ in3, const float* __restrict__ skin,
                           float* __restrict__ out, int OH, int OW,
                           const float* __restrict__ dw, const float* __restrict__ db,
                           const float* __restrict__ sw, const float* __restrict__ sb)
{
    __shared__ float s_in[8][33][33];
    __shared__ float s_w[4][8][9];
    __shared__ float s_sw[4][8];
    int IH = 2*OH, IW = 2*OW;
    int tx = threadIdx.x, ty = threadIdx.y, tid = ty*16 + tx;
    int x0 = blockIdx.x*16, y0 = blockIdx.y*16;
    int bb = blockIdx.z >> 4;
    int cog = blockIdx.z & 15;
    float acc[4] = {0.f,0.f,0.f,0.f};
    const float* inb = in3 + (size_t)bb*CC*IH*IW;
    const float* skb = skin + (size_t)bb*CC*OH*OW;
    int oy = y0 + ty, ox = x0 + tx;

    for (int c0 = 0; c0 < CC; c0 += 8) {
        for (int i = tid; i < 8*33*33; i += 256) {
            int ci = i / 1089, rem = i % 1089, r = rem / 33, c = rem % 33;
            int y = 2*y0 - 1 + r, x = 2*x0 - 1 + c;
            float v = 0.f;
            if (y >= 0 && y < IH && x >= 0 && x < IW)
                v = inb[(size_t)(c0+ci)*IH*IW + y*IW + x];
            s_in[ci][r][c] = v;
        }
        for (int i = tid; i < 288; i += 256) {
            int col = i / 72, rem = i % 72, ci = rem / 9, k = rem % 9;
            s_w[col][ci][k] = dw[((size_t)(cog*4+col)*CC + c0+ci)*9 + k];
        }
        if (tid < 32) {
            int col = tid >> 3, ci = tid & 7;
            s_sw[col][ci] = sw[(cog*4+col)*CC + c0+ci];
        }
        __syncthreads();
        #pragma unroll
        for (int ci = 0; ci < 8; ci++) {
            float v[9];
            #pragma unroll
            for (int j = 0; j < 9; j++) v[j] = s_in[ci][2*ty + j/3][2*tx + j%3];
            float sv = skb[(size_t)(c0+ci)*OH*OW + oy*OW + ox];
            #pragma unroll
            for (int col = 0; col < 4; col++) {
                float a = acc[col];
                #pragma unroll
                for (int k = 0; k < 9; k++) a += v[k]*s_w[col][ci][k];
                a += sv * s_sw[col][ci];
                acc[col] = a;
            }
        }
        __syncthreads();
    }
    float* ob = out + (size_t)bb*CC*OH*OW;
    #pragma unroll
    for (int col = 0; col < 4; col++) {
        int co = cog*4 + col;
        ob[(size_t)co*OH*OW + oy*OW + ox] = acc[col] + db[co] + sb[co];
    }
}

// ================= channel-last transpose: [b][c][p] -> [b][p][c] =================
// block (32,8), grid (P/32, 2, B)
__global__ void to_chlast(const float* __restrict__ in, float* __restrict__ out, int P)
{
    __shared__ float t[32][33];
    int p0 = blockIdx.x*32;
    int c0 = blockIdx.y*32;
    int b  = blockIdx.z;
    const float* ib = in + ((size_t)b*CC + c0)*(size_t)P + p0;
    for (int i = threadIdx.y; i < 32; i += 8)
        t[i][threadIdx.x] = ib[(size_t)i*P + threadIdx.x];
    __syncthreads();
    float* ob = out + ((size_t)b*P + p0)*CC + c0;
    for (int i = threadIdx.y; i < 32; i += 8)
        ob[(size_t)i*CC + threadIdx.x] = t[threadIdx.x][i];
}

// ================= weight prep: transpose (fp32) =================
__global__ void prep_wt(const float* __restrict__ w0, const float* __restrict__ w1,
                        const float* __restrict__ w2, const float* __restrict__ w3)
{
    int i = blockIdx.x*256 + threadIdx.x;
    int total = 256*K0P + 3*256*256;
    if (i >= total) return;
    float v;
    if (i < 256*K0P) {
        int n = i / K0P, k = i % K0P;
        v = (k < 260) ? w0[(size_t)k*256 + n] : 0.0f;
    } else {
        int j = i - 256*K0P;
        int l = j / 65536, r = j % 65536;
        int n = r / 256, k = r % 256;
        const float* ws = (l == 0) ? w1 : (l == 1) ? w2 : w3;
        v = ws[(size_t)k*256 + n];
    }
    g_Wt[i] = v;
}

// ================= gather + build X (coalesced channel-last reads) =================
__device__ __forceinline__ int nidx(float cc, float n)
{
    float f = rintf((cc + 1.0f)*(n*0.5f) - 0.5f);
    f = fminf(fmaxf(f, 0.0f), n - 1.0f);
    return (int)f;
}

__global__ void gather_build(const float* __restrict__ coord, const float* __restrict__ cell)
{
    int tid = threadIdx.x;
    int row = blockIdx.x*4 + (tid >> 6);
    int c   = tid & 63;
    int s   = row & 3;
    int bq  = row >> 2;
    int b   = bq >> 14;
    float cy = coord[(size_t)bq*2 + 0];
    float cx = coord[(size_t)bq*2 + 1];
    float vx = (s & 2) ? 1.f : -1.f;
    float vy = (s & 1) ? 1.f : -1.f;
    const float RX = 1.0f/48.0f;
    float sy = fminf(fmaxf(cy + vx*RX + 1e-6f, -1.f + 1e-6f), 1.f - 1e-6f);
    float sx = fminf(fmaxf(cx + vy*RX + 1e-6f, -1.f + 1e-6f), 1.f - 1e-6f);
    int iy0 = nidx(sy, 48.f),  ix0 = nidx(sx, 48.f);
    int iy1 = nidx(sy, 96.f),  ix1 = nidx(sx, 96.f);
    int iy2 = nidx(sy, 192.f), ix2 = nidx(sx, 192.f);
    int iy3 = nidx(sy, 384.f), ix3 = nidx(sx, 384.f);

    float* xr = g_X + (size_t)row*K0P;
    xr[c]       = g_featL [((size_t)b*2304   + iy0*48  + ix0)*CC + c];
    xr[64 + c]  = g_feat5L[((size_t)b*9216   + iy1*96  + ix1)*CC + c];
    xr[128 + c] = g_feat4L[((size_t)b*36864  + iy2*192 + ix2)*CC + c];
    xr[192 + c] = g_feat3L[((size_t)b*147456 + iy3*384 + ix3)*CC + c];
    if (c == 0) {
        float qcy = -1.f + (2.f*iy0 + 1.f)/48.f;
        float qcx = -1.f + (2.f*ix0 + 1.f)/48.f;
        float ry_ = (cy - qcy)*48.f;
        float rx_ = (cx - qcx)*48.f;
        xr[256] = ry_;
        xr[257] = rx_;
        xr[258] = cell[(size_t)bq*2 + 0]*48.f;
        xr[259] = cell[(size_t)bq*2 + 1]*48.f;
        g_area[row] = fabsf(ry_*rx_) + 1e-9f;
    }
    if (c < 12) xr[260 + c] = 0.0f;   // pad to 272
}

// ================= scalar-FFMA SGEMM, 128x128 tile, 8x8/thread =================
__global__ void __launch_bounds__(256)
gemm_f32(const float* __restrict__ A, const float* __restrict__ Wt,
         const float* __restrict__ bias, float* __restrict__ C, int K)
{
    __shared__ float As[2][8][128];
    __shared__ float Bs[2][8][128];
    int tid = threadIdx.x;
    int tx = tid & 15, ty = tid >> 4;
    int m0 = blockIdx.y*128, n0 = blockIdx.x*128;
    int lrow = tid >> 1, lk = (tid & 1)*4;
    const float* ap = A  + (size_t)(m0 + lrow)*K + lk;
    const float* bp = Wt + (size_t)(n0 + lrow)*K + lk;
    int NK = K >> 3;

    float acc[8][8];
    #pragma unroll
    for (int i = 0; i < 8; i++)
        #pragma unroll
        for (int j = 0; j < 8; j++) acc[i][j] = 0.f;

    float4 av = *(const float4*)ap;
    float4 bv = *(const float4*)bp;

    for (int it = 0; it < NK; it++) {
        int buf = it & 1;
        As[buf][lk+0][lrow] = av.x;
        As[buf][lk+1][lrow] = av.y;
        As[buf][lk+2][lrow] = av.z;
        As[buf][lk+3][lrow] = av.w;
        Bs[buf][lk+0][lrow] = bv.x;
        Bs[buf][lk+1][lrow] = bv.y;
        Bs[buf][lk+2][lrow] = bv.z;
        Bs[buf][lk+3][lrow] = bv.w;
        if (it + 1 < NK) {
            av = *(const float4*)(ap + (it+1)*8);
            bv = *(const float4*)(bp + (it+1)*8);
        }
        __syncthreads();
        #pragma unroll
        for (int kk = 0; kk < 8; kk++) {
            float a[8], b[8];
            *(float4*)(a)   = *(const float4*)&As[buf][kk][ty*4];
            *(float4*)(a+4) = *(const float4*)&As[buf][kk][ty*4 + 64];
            *(float4*)(b)   = *(const float4*)&Bs[buf][kk][tx*4];
            *(float4*)(b+4) = *(const float4*)&Bs[buf][kk][tx*4 + 64];
            #pragma unroll
            for (int i = 0; i < 8; i++)
                #pragma unroll
                for (int j = 0; j < 8; j++)
                    acc[i][j] += a[i]*b[j];
        }
    }

    float bn[8];
    #pragma unroll
    for (int j = 0; j < 8; j++)
        bn[j] = bias[n0 + ((j < 4) ? tx*4 + j : 64 + tx*4 + j - 4)];
    #pragma unroll
    for (int i = 0; i < 8; i++) {
        int m = m0 + ((i < 4) ? ty*4 + i : 64 + ty*4 + i - 4);
        float* cr = C + (size_t)m*HID + n0;
        float4 q0 = make_float4(fmaxf(acc[i][0] + bn[0], 0.f),
                                fmaxf(acc[i][1] + bn[1], 0.f),
                                fmaxf(acc[i][2] + bn[2], 0.f),
                                fmaxf(acc[i][3] + bn[3], 0.f));
        float4 q1 = make_float4(fmaxf(acc[i][4] + bn[4], 0.f),
                                fmaxf(acc[i][5] + bn[5], 0.f),
                                fmaxf(acc[i][6] + bn[6], 0.f),
                                fmaxf(acc[i][7] + bn[7], 0.f));
        *(float4*)(cr + tx*4)      = q0;
        *(float4*)(cr + 64 + tx*4) = q1;
    }
}

// ================= last layer: [M,256]@[256,3]+b =================
__global__ void mlp_last(const float* __restrict__ Hin, const float* __restrict__ W4,
                         const float* __restrict__ b4)
{
    int warp = threadIdx.x >> 5, lane = threadIdx.x & 31;
    int row = blockIdx.x*4 + warp;
    const float* hr = Hin + (size_t)row*HID;
    float a0 = 0.f, a1 = 0.f, a2 = 0.f;
    for (int k = lane; k < HID; k += 32) {
        float h = hr[k];
        a0 += h*W4[k*3 + 0];
        a1 += h*W4[k*3 + 1];
        a2 += h*W4[k*3 + 2];
    }
    #pragma unroll
    for (int o = 16; o; o >>= 1) {
        a0 += __shfl_down_sync(0xffffffffu, a0, o);
        a1 += __shfl_down_sync(0xffffffffu, a1, o);
        a2 += __shfl_down_sync(0xffffffffu, a2, o);
    }
    if (lane == 0) {
        g_P[(size_t)row*3 + 0] = a0 + b4[0];
        g_P[(size_t)row*3 + 1] = a1 + b4[1];
        g_P[(size_t)row*3 + 2] = a2 + b4[2];
    }
}

// ================= ensemble + bilinear border skip =================
__global__ void ensemble(const float* __restrict__ coord, const float* __restrict__ inp,
                         float* __restrict__ out)
{
    int bq = blockIdx.x*256 + threadIdx.x;
    if (bq >= BB*QQ) return;
    int b = bq >> 14;
    float cy = coord[(size_t)bq*2 + 0];
    float cx = coord[(size_t)bq*2 + 1];
    int base = bq*4;
    float a0 = g_area[base+0], a1 = g_area[base+1], a2 = g_area[base+2], a3 = g_area[base+3];
    float inv = 1.0f/(a0 + a1 + a2 + a3);
    float w0 = a3*inv, w1 = a2*inv, w2 = a1*inv, w3 = a0*inv;
    float r[3];
    #pragma unroll
    for (int c = 0; c < 3; c++) {
        r[c] = g_P[(size_t)(base+0)*3 + c]*w0
             + g_P[(size_t)(base+1)*3 + c]*w1
             + g_P[(size_t)(base+2)*3 + c]*w2
             + g_P[(size_t)(base+3)*3 + c]*w3;
    }
    float fy = fminf(fmaxf((cy + 1.f)*24.f - 0.5f, 0.f), 47.f);
    float fx = fminf(fmaxf((cx + 1.f)*24.f - 0.5f, 0.f), 47.f);
    float y0f = floorf(fy), x0f = floorf(fx);
    int y0 = (int)y0f, x0 = (int)x0f;
    float wy = fy - y0f, wx = fx - x0f;
    int y1 = min(y0 + 1, 47), x1 = min(x0 + 1, 47);
    const float* ib = inp + (size_t)b*3*H0*W0;
    #pragma unroll
    for (int ch = 0; ch < 3; ch++) {
        const float* p = ib + ch*H0*W0;
        float v00 = p[y0*48 + x0], v01 = p[y0*48 + x1];
        float v10 = p[y1*48 + x0], v11 = p[y1*48 + x1];
        r[ch] += v00*(1.f - wy)*(1.f - wx) + v01*(1.f - wy)*wx
               + v10*wy*(1.f - wx) + v11*wy*wx;
        out[(size_t)bq*3 + ch] = r[ch];
    }
}

// ================= host launch =================
extern "C" void kernel_launch(void* const* d_in, const int* in_sizes, int n_in,
                              void* d_out, int out_size)
{
    const float* inp     = (const float*)d_in[0];
    const float* coord   = (const float*)d_in[1];
    const float* cell    = (const float*)d_in[2];
    const float* enc_w   = (const float*)d_in[3];
    const float* enc_b   = (const float*)d_in[4];
    const float* up1_w   = (const float*)d_in[5];
    const float* up1_b   = (const float*)d_in[6];
    const float* up2_w   = (const float*)d_in[7];
    const float* up2_b   = (const float*)d_in[8];
    const float* up3_w   = (const float*)d_in[9];
    const float* up3_b   = (const float*)d_in[10];
    const float* skip1_w = (const float*)d_in[11];
    const float* skip1_b = (const float*)d_in[12];
    const float* skip2_w = (const float*)d_in[13];
    const float* skip2_b = (const float*)d_in[14];
    const float* down4_w = (const float*)d_in[15];
    const float* down4_b = (const float*)d_in[16];
    const float* down5_w = (const float*)d_in[17];
    const float* down5_b = (const float*)d_in[18];
    const float* mlp_w0  = (const float*)d_in[19];
    const float* mlp_b0  = (const float*)d_in[20];
    const float* mlp_w1  = (const float*)d_in[21];
    const float* mlp_b1  = (const float*)d_in[22];
    const float* mlp_w2  = (const float*)d_in[23];
    const float* mlp_b2  = (const float*)d_in[24];
    const float* mlp_w3  = (const float*)d_in[25];
    const float* mlp_b3  = (const float*)d_in[26];
    const float* mlp_w4  = (const float*)d_in[27];
    const float* mlp_b4  = (const float*)d_in[28];
    float* out = (float*)d_out;

    float *p_feat, *p_feat1, *p_feat2, *p_feat3, *p_feat4, *p_feat5;
    float *p_featL, *p_feat3L, *p_feat4L, *p_feat5L;
    float *p_X, *p_H0, *p_H1, *p_Wt;
    cudaGetSymbolAddress((void**)&p_feat,  g_feat);
    cudaGetSymbolAddress((void**)&p_feat1, g_feat1);
    cudaGetSymbolAddress((void**)&p_feat2, g_feat2);
    cudaGetSymbolAddress((void**)&p_feat3, g_feat3);
    cudaGetSymbolAddress((void**)&p_feat4, g_feat4);
    cudaGetSymbolAddress((void**)&p_feat5, g_feat5);
    cudaGetSymbolAddress((void**)&p_featL,  g_featL);
    cudaGetSymbolAddress((void**)&p_feat3L, g_feat3L);
    cudaGetSymbolAddress((void**)&p_feat4L, g_feat4L);
    cudaGetSymbolAddress((void**)&p_feat5L, g_feat5L);
    cudaGetSymbolAddress((void**)&p_X,  g_X);
    cudaGetSymbolAddress((void**)&p_H0, g_H0b);
    cudaGetSymbolAddress((void**)&p_H1, g_H1b);
    cudaGetSymbolAddress((void**)&p_Wt, g_Wt);

    // weight prep (independent of convs)
    {
        int total = 256*K0P + 3*256*256;
        prep_wt<<<(total + 255)/256, 256>>>(mlp_w0, mlp_w1, mlp_w2, mlp_w3);
    }
    // encoder + pyramid
    {
        int total = BB*CC*H0*W0;
        enc_conv<<<(total + 255)/256, 256>>>(inp, enc_w, enc_b);
        up_conv_ps5<<<dim3(2, 2, BB*64), 128>>>(p_feat,  p_feat1, 48, 48,  up1_w, up1_b);
        up_conv_ps5<<<dim3(3, 3, BB*64), 128>>>(p_feat1, p_feat2, 96, 96,  up2_w, up2_b);
        up_conv_ps5<<<dim3(6, 6, BB*64), 128>>>(p_feat2, p_feat3, 192,192, up3_w, up3_b);
        dim3 blk(16,16);
        down_fused<<<dim3(12, 12, BB*16), blk>>>(p_feat3, p_feat2, p_feat4, 192, 192,
                                                 down4_w, down4_b, skip1_w, skip1_b);
        down_fused<<<dim3(6,  6,  BB*16), blk>>>(p_feat4, p_feat1, p_feat5, 96, 96,
                                                 down5_w, down5_b, skip2_w, skip2_b);
    }
    // channel-last transposes for coalesced gather
    {
        dim3 tb(32, 8);
        to_chlast<<<dim3(2304/32,   2, BB), tb>>>(p_feat,  p_featL,  2304);
        to_chlast<<<dim3(9216/32,   2, BB), tb>>>(p_feat5, p_feat5L, 9216);
        to_chlast<<<dim3(36864/32,  2, BB), tb>>>(p_feat4, p_feat4L, 36864);
        to_chlast<<<dim3(147456/32, 2, BB), tb>>>(p_feat3, p_feat3L, 147456);
    }
    // gather + build X (fp32, padded to 272)
    gather_build<<<MROWS/4, 256>>>(coord, cell);

    // MLP hidden layers: scalar-FFMA 128x128 GEMM
    {
        dim3 grid(HID/128, MROWS/128);   // (2, 2048)
        const float* W1 = p_Wt + 256*K0P;
        const float* W2 = W1 + 65536;
        const float* W3 = W2 + 65536;
        gemm_f32<<<grid, 256>>>(p_X,  p_Wt, mlp_b0, p_H0, K0P);
        gemm_f32<<<grid, 256>>>(p_H0, W1,   mlp_b1, p_H1, 256);
        gemm_f32<<<grid, 256>>>(p_H1, W2,   mlp_b2, p_H0, 256);
        gemm_f32<<<grid, 256>>>(p_H0, W3,   mlp_b3, p_H1, 256);
    }
    // last layer + ensemble
    mlp_last<<<MROWS/4, 128>>>(p_H1, mlp_w4, mlp_b4);
    ensemble<<<(BB*QQ + 255)/256, 256>>>(coord, inp, out);
}

// round 11
// speedup vs baseline: 1.9181x; 1.0826x over previous
#include <cuda_runtime.h>
#include <cuda_bf16.h>
#include <cstdint>

// ---------------- problem constants ----------------
#define BB     4
#define CC     64
#define H0     48
#define W0     48
#define QQ     16384
#define MROWS  (BB*QQ*4)     // 262144
#define HID    256
#define K0P    272           // layer-0 K (260) padded to multiple of 8

// ---------------- scratch ----------------
__device__ float g_feat [BB*CC*H0*W0];
__device__ float g_feat1[BB*CC*96*96];
__device__ float g_feat2[BB*CC*192*192];
__device__ float g_feat3[BB*CC*384*384];
__device__ float g_feat4[BB*CC*192*192];
__device__ float g_feat5[BB*CC*96*96];
// channel-last copies for coalesced gather
__device__ float g_featL [BB*48*48*CC];
__device__ float g_feat5L[BB*96*96*CC];
__device__ float g_feat4L[BB*192*192*CC];
__device__ float g_feat3L[BB*384*384*CC];
__device__ float g_X  [(size_t)MROWS*K0P];
__device__ float g_H0b[(size_t)MROWS*HID];
__device__ float g_H1b[(size_t)MROWS*HID];
__device__ float g_Wt [256*K0P + 3*256*256];   // transposed weights [n][k]
__device__ float g_area[MROWS];

// ================= enc conv (tiny, unchanged) =================
__global__ void enc_conv(const float* __restrict__ inp,
                         const float* __restrict__ w,
                         const float* __restrict__ b)
{
    int idx = blockIdx.x*256 + threadIdx.x;
    if (idx >= BB*CC*H0*W0) return;
    int x  = idx % W0;
    int y  = (idx / W0) % H0;
    int co = (idx / (H0*W0)) % CC;
    int bb = idx / (H0*W0*CC);
    float acc = b[co];
    const float* ib = inp + (size_t)bb*3*H0*W0;
    #pragma unroll
    for (int ci = 0; ci < 3; ci++) {
        #pragma unroll
        for (int ky = 0; ky < 3; ky++) {
            int yy = y + ky - 1;
            if (yy < 0 || yy >= H0) continue;
            #pragma unroll
            for (int kx = 0; kx < 3; kx++) {
                int xx = x + kx - 1;
                if (xx < 0 || xx >= W0) continue;
                acc += ib[ci*H0*W0 + yy*W0 + xx] * w[(co*3 + ci)*9 + ky*3 + kx];
            }
        }
    }
    g_feat[idx] = acc;
}

// ================= up conv 3x3 (64->256) + pixel shuffle (R10, proven) =================
__global__ void __launch_bounds__(128)
up_conv_ps5(const float* __restrict__ in, float* __restrict__ out,
            int H, int W,
            const float* __restrict__ w, const float* __restrict__ bias)
{
    __shared__ float s_w[64][4][12];
    __shared__ float s_in[4][34][36];
    int tid = threadIdx.x;
    int tx = tid & 7, ty = tid >> 3;
    int x0 = blockIdx.x*32, y0 = blockIdx.y*32;
    int bb = blockIdx.z >> 6;
    int cog = blockIdx.z & 63;
    const float* inb = in + (size_t)bb*CC*H*W;
    int bxp = x0 + tx*4;
    int byp = y0 + ty*2;

    for (int i = tid; i < 64*36; i += 128) {
        int ci = i / 36, rem = i % 36;
        int col = rem / 9, k = rem % 9;
        s_w[ci][col][k] = w[((size_t)(cog*4 + col)*CC + ci)*9 + k];
    }

    float acc[4][8];
    #pragma unroll
    for (int c = 0; c < 4; c++)
        #pragma unroll
        for (int p = 0; p < 8; p++) acc[c][p] = 0.f;

    for (int c0 = 0; c0 < CC; c0 += 4) {
        __syncthreads();
        for (int idx = tid; idx < 1224; idx += 128) {
            int seg = idx % 9;
            int rc  = idx / 9;
            int r   = rc % 34;
            int ci  = rc / 34;
            int y = y0 + r - 1;
            bool yok = (y >= 0) && (y < H);
            const float* grow = inb + (size_t)(c0+ci)*H*W + (size_t)y*W;
            float* srow = &s_in[ci][r][0];
            if (seg < 8) {
                int x = x0 + seg*4;
                float4 v = make_float4(0.f, 0.f, 0.f, 0.f);
                if (yok) {
                    if (x + 3 < W) {
                        v = *(const float4*)(grow + x);
                    } else {
                        if (x + 0 < W) v.x = grow[x + 0];
                        if (x + 1 < W) v.y = grow[x + 1];
                        if (x + 2 < W) v.z = grow[x + 2];
                        if (x + 3 < W) v.w = grow[x + 3];
                    }
                }
                srow[1 + seg*4 + 0] = v.x;
                srow[1 + seg*4 + 1] = v.y;
                srow[1 + seg*4 + 2] = v.z;
                srow[1 + seg*4 + 3] = v.w;
            } else {
                float lft = 0.f, rgt = 0.f;
                if (yok) {
                    if (x0 > 0)       lft = grow[x0 - 1];
                    if (x0 + 32 < W)  rgt = grow[x0 + 32];
                }
                srow[0]  = lft;
                srow[33] = rgt;
            }
        }
        __syncthreads();
        #pragma unroll
        for (int ci = 0; ci < 4; ci++) {
            float v[4][8];
            #pragma unroll
            for (int r = 0; r < 4; r++) {
                float4 p0 = *(const float4*)&s_in[ci][ty*2 + r][tx*4];
                float4 p1 = *(const float4*)&s_in[ci][ty*2 + r][tx*4 + 4];
                v[r][0] = p0.x; v[r][1] = p0.y; v[r][2] = p0.z; v[r][3] = p0.w;
                v[r][4] = p1.x; v[r][5] = p1.y; v[r][6] = p1.z; v[r][7] = p1.w;
            }
            #pragma unroll
            for (int col = 0; col < 4; col++) {
                float4 w0 = *(const float4*)&s_w[c0+ci][col][0];
                float4 w1 = *(const float4*)&s_w[c0+ci][col][4];
                float4 w2 = *(const float4*)&s_w[c0+ci][col][8];
                float wr[9] = {w0.x, w0.y, w0.z, w0.w, w1.x, w1.y, w1.z, w1.w, w2.x};
                #pragma unroll
                for (int py = 0; py < 2; py++)
                    #pragma unroll
                    for (int px = 0; px < 4; px++) {
                        float a = acc[col][py*4 + px];
                        #pragma unroll
                        for (int ky = 0; ky < 3; ky++)
                            #pragma unroll
                            for (int kx = 0; kx < 3; kx++)
                                a += v[py+ky][px+kx] * wr[ky*3+kx];
                        acc[col][py*4 + px] = a;
                    }
            }
        }
    }

    if (bxp < W) {
        float b4[4];
        #pragma unroll
        for (int c = 0; c < 4; c++) b4[c] = bias[cog*4 + c];
        int H2 = 2*H, W2 = 2*W;
        float* ob = out + ((size_t)bb*CC + cog)*H2*W2;
        #pragma unroll
        for (int py = 0; py < 2; py++) {
            int yo = byp + py;
            if (yo >= H) continue;
            #pragma unroll
            for (int r = 0; r < 2; r++) {
                float* orow = ob + (size_t)(2*yo + r)*W2 + 2*bxp;
                float4 q0 = make_float4(acc[2*r+0][py*4+0] + b4[2*r+0],
                                        acc[2*r+1][py*4+0] + b4[2*r+1],
                                        acc[2*r+0][py*4+1] + b4[2*r+0],
                                        acc[2*r+1][py*4+1] + b4[2*r+1]);
                float4 q1 = make_float4(acc[2*r+0][py*4+2] + b4[2*r+0],
                                        acc[2*r+1][py*4+2] + b4[2*r+1],
                                        acc[2*r+0][py*4+3] + b4[2*r+0],
                                        acc[2*r+1][py*4+3] + b4[2*r+1]);
                *(float4*)(orow)     = q0;
                *(float4*)(orow + 4) = q1;
            }
        }
    }
}

// ================= stride2 conv3x3 + 1x1 skip — modernized loader =================
// grid (OW/16, OH/16, B*16), block (16,16). 4 c_out/thread.
// Input rows [2x0-1 .. 2x0+31]: guarded left scalar + 8 aligned float4 segments.
__global__ void down_fused2(const float* __restrict__ in3, const float* __restrict__ skin,
                            float* __restrict__ out, int OH, int OW,
                            const float* __restrict__ dw, const float* __restrict__ db,
                            const float* __restrict__ sw, const float* __restrict__ sb)
{
    __shared__ float s_in[8][33][36];     // 38 KB, rows padded for alignment
    __shared__ float s_w[4][8][9];
    __shared__ float s_sw[4][8];
    int IH = 2*OH, IW = 2*OW;
    int tx = threadIdx.x, ty = threadIdx.y, tid = ty*16 + tx;
    int x0 = blockIdx.x*16, y0 = blockIdx.y*16;
    int bb = blockIdx.z >> 4;
    int cog = blockIdx.z & 15;
    float acc[4] = {0.f,0.f,0.f,0.f};
    const float* inb = in3 + (size_t)bb*CC*IH*IW;
    const float* skb = skin + (size_t)bb*CC*OH*OW;
    int oy = y0 + ty, ox = x0 + tx;
    int gx0 = 2*x0;                       // 32-aligned global x base

    for (int c0 = 0; c0 < CC; c0 += 8) {
        __syncthreads();
        // ---- vectorized input loader: 8ci x 33rows x 9segs ----
        for (int idx = tid; idx < 8*33*9; idx += 256) {
            int seg = idx % 9;
            int rc  = idx / 9;
            int r   = rc % 33;
            int ci  = rc / 33;
            int y = 2*y0 - 1 + r;
            bool yok = (y >= 0) && (y < IH);
            const float* grow = inb + (size_t)(c0+ci)*IH*IW + (size_t)y*IW;
            float* srow = &s_in[ci][r][0];
            if (seg < 8) {
                // cols 1+4seg .. 4+4seg  <-> gx = gx0 + 4seg + u  (always < IW)
                float4 v = make_float4(0.f, 0.f, 0.f, 0.f);
                if (yok) v = *(const float4*)(grow + gx0 + seg*4);
                srow[1 + seg*4 + 0] = v.x;
                srow[1 + seg*4 + 1] = v.y;
                srow[1 + seg*4 + 2] = v.z;
                srow[1 + seg*4 + 3] = v.w;
            } else {
                float lft = 0.f;
                if (yok && gx0 > 0) lft = grow[gx0 - 1];
                srow[0] = lft;    // gx = gx0 - 1
            }
        }
        // weights per chunk (cheap)
        for (int i = tid; i < 288; i += 256) {
            int col = i / 72, rem = i % 72, ci = rem / 9, k = rem % 9;
            s_w[col][ci][k] = dw[((size_t)(cog*4+col)*CC + c0+ci)*9 + k];
        }
        if (tid < 32) {
            int col = tid >> 3, ci = tid & 7;
            s_sw[col][ci] = sw[(cog*4+col)*CC + c0+ci];
        }
        __syncthreads();
        #pragma unroll
        for (int ci = 0; ci < 8; ci++) {
            float v[9];
            #pragma unroll
            for (int j = 0; j < 9; j++) v[j] = s_in[ci][2*ty + j/3][2*tx + j%3];
            float sv = skb[(size_t)(c0+ci)*OH*OW + oy*OW + ox];
            #pragma unroll
            for (int col = 0; col < 4; col++) {
                float a = acc[col];
                #pragma unroll
                for (int k = 0; k < 9; k++) a += v[k]*s_w[col][ci][k];
                a += sv * s_sw[col][ci];
                acc[col] = a;
            }
        }
    }
    float* ob = out + (size_t)bb*CC*OH*OW;
    #pragma unroll
    for (int col = 0; col < 4; col++) {
        int co = cog*4 + col;
        ob[(size_t)co*OH*OW + oy*OW + ox] = acc[col] + db[co] + sb[co];
    }
}

// ================= channel-last transpose: [b][c][p] -> [b][p][c] =================
__global__ void to_chlast(const float* __restrict__ in, float* __restrict__ out, int P)
{
    __shared__ float t[32][33];
    int p0 = blockIdx.x*32;
    int c0 = blockIdx.y*32;
    int b  = blockIdx.z;
    const float* ib = in + ((size_t)b*CC + c0)*(size_t)P + p0;
    for (int i = threadIdx.y; i < 32; i += 8)
        t[i][threadIdx.x] = ib[(size_t)i*P + threadIdx.x];
    __syncthreads();
    float* ob = out + ((size_t)b*P + p0)*CC + c0;
    for (int i = threadIdx.y; i < 32; i += 8)
        ob[(size_t)i*CC + threadIdx.x] = t[threadIdx.x][i];
}

// ================= weight prep: transpose (fp32) =================
__global__ void prep_wt(const float* __restrict__ w0, const float* __restrict__ w1,
                        const float* __restrict__ w2, const float* __restrict__ w3)
{
    int i = blockIdx.x*256 + threadIdx.x;
    int total = 256*K0P + 3*256*256;
    if (i >= total) return;
    float v;
    if (i < 256*K0P) {
        int n = i / K0P, k = i % K0P;
        v = (k < 260) ? w0[(size_t)k*256 + n] : 0.0f;
    } else {
        int j = i - 256*K0P;
        int l = j / 65536, r = j % 65536;
        int n = r / 256, k = r % 256;
        const float* ws = (l == 0) ? w1 : (l == 1) ? w2 : w3;
        v = ws[(size_t)k*256 + n];
    }
    g_Wt[i] = v;
}

// ================= gather + build X (coalesced channel-last reads) =================
__device__ __forceinline__ int nidx(float cc, float n)
{
    float f = rintf((cc + 1.0f)*(n*0.5f) - 0.5f);
    f = fminf(fmaxf(f, 0.0f), n - 1.0f);
    return (int)f;
}

__global__ void gather_build(const float* __restrict__ coord, const float* __restrict__ cell)
{
    int tid = threadIdx.x;
    int row = blockIdx.x*4 + (tid >> 6);
    int c   = tid & 63;
    int s   = row & 3;
    int bq  = row >> 2;
    int b   = bq >> 14;
    float cy = coord[(size_t)bq*2 + 0];
    float cx = coord[(size_t)bq*2 + 1];
    float vx = (s & 2) ? 1.f : -1.f;
    float vy = (s & 1) ? 1.f : -1.f;
    const float RX = 1.0f/48.0f;
    float sy = fminf(fmaxf(cy + vx*RX + 1e-6f, -1.f + 1e-6f), 1.f - 1e-6f);
    float sx = fminf(fmaxf(cx + vy*RX + 1e-6f, -1.f + 1e-6f), 1.f - 1e-6f);
    int iy0 = nidx(sy, 48.f),  ix0 = nidx(sx, 48.f);
    int iy1 = nidx(sy, 96.f),  ix1 = nidx(sx, 96.f);
    int iy2 = nidx(sy, 192.f), ix2 = nidx(sx, 192.f);
    int iy3 = nidx(sy, 384.f), ix3 = nidx(sx, 384.f);

    float* xr = g_X + (size_t)row*K0P;
    xr[c]       = g_featL [((size_t)b*2304   + iy0*48  + ix0)*CC + c];
    xr[64 + c]  = g_feat5L[((size_t)b*9216   + iy1*96  + ix1)*CC + c];
    xr[128 + c] = g_feat4L[((size_t)b*36864  + iy2*192 + ix2)*CC + c];
    xr[192 + c] = g_feat3L[((size_t)b*147456 + iy3*384 + ix3)*CC + c];
    if (c == 0) {
        float qcy = -1.f + (2.f*iy0 + 1.f)/48.f;
        float qcx = -1.f + (2.f*ix0 + 1.f)/48.f;
        float ry_ = (cy - qcy)*48.f;
        float rx_ = (cx - qcx)*48.f;
        xr[256] = ry_;
        xr[257] = rx_;
        xr[258] = cell[(size_t)bq*2 + 0]*48.f;
        xr[259] = cell[(size_t)bq*2 + 1]*48.f;
        g_area[row] = fabsf(ry_*rx_) + 1e-9f;
    }
    if (c < 12) xr[260 + c] = 0.0f;   // pad to 272
}

// ================= scalar-FFMA SGEMM, 128x128 tile, 8x8/thread =================
__global__ void __launch_bounds__(256)
gemm_f32(const float* __restrict__ A, const float* __restrict__ Wt,
         const float* __restrict__ bias, float* __restrict__ C, int K)
{
    __shared__ float As[2][8][128];
    __shared__ float Bs[2][8][128];
    int tid = threadIdx.x;
    int tx = tid & 15, ty = tid >> 4;
    int m0 = blockIdx.y*128, n0 = blockIdx.x*128;
    int lrow = tid >> 1, lk = (tid & 1)*4;
    const float* ap = A  + (size_t)(m0 + lrow)*K + lk;
    const float* bp = Wt + (size_t)(n0 + lrow)*K + lk;
    int NK = K >> 3;

    float acc[8][8];
    #pragma unroll
    for (int i = 0; i < 8; i++)
        #pragma unroll
        for (int j = 0; j < 8; j++) acc[i][j] = 0.f;

    float4 av = *(const float4*)ap;
    float4 bv = *(const float4*)bp;

    for (int it = 0; it < NK; it++) {
        int buf = it & 1;
        As[buf][lk+0][lrow] = av.x;
        As[buf][lk+1][lrow] = av.y;
        As[buf][lk+2][lrow] = av.z;
        As[buf][lk+3][lrow] = av.w;
        Bs[buf][lk+0][lrow] = bv.x;
        Bs[buf][lk+1][lrow] = bv.y;
        Bs[buf][lk+2][lrow] = bv.z;
        Bs[buf][lk+3][lrow] = bv.w;
        if (it + 1 < NK) {
            av = *(const float4*)(ap + (it+1)*8);
            bv = *(const float4*)(bp + (it+1)*8);
        }
        __syncthreads();
        #pragma unroll
        for (int kk = 0; kk < 8; kk++) {
            float a[8], b[8];
            *(float4*)(a)   = *(const float4*)&As[buf][kk][ty*4];
            *(float4*)(a+4) = *(const float4*)&As[buf][kk][ty*4 + 64];
            *(float4*)(b)   = *(const float4*)&Bs[buf][kk][tx*4];
            *(float4*)(b+4) = *(const float4*)&Bs[buf][kk][tx*4 + 64];
            #pragma unroll
            for (int i = 0; i < 8; i++)
                #pragma unroll
                for (int j = 0; j < 8; j++)
                    acc[i][j] += a[i]*b[j];
        }
    }

    float bn[8];
    #pragma unroll
    for (int j = 0; j < 8; j++)
        bn[j] = bias[n0 + ((j < 4) ? tx*4 + j : 64 + tx*4 + j - 4)];
    #pragma unroll
    for (int i = 0; i < 8; i++) {
        int m = m0 + ((i < 4) ? ty*4 + i : 64 + ty*4 + i - 4);
        float* cr = C + (size_t)m*HID + n0;
        float4 q0 = make_float4(fmaxf(acc[i][0] + bn[0], 0.f),
                                fmaxf(acc[i][1] + bn[1], 0.f),
                                fmaxf(acc[i][2] + bn[2], 0.f),
                                fmaxf(acc[i][3] + bn[3], 0.f));
        float4 q1 = make_float4(fmaxf(acc[i][4] + bn[4], 0.f),
                                fmaxf(acc[i][5] + bn[5], 0.f),
                                fmaxf(acc[i][6] + bn[6], 0.f),
                                fmaxf(acc[i][7] + bn[7], 0.f));
        *(float4*)(cr + tx*4)      = q0;
        *(float4*)(cr + 64 + tx*4) = q1;
    }
}

// ================= fused last layer + ensemble + bilinear skip =================
// one block (128 thr = 4 warps) per query; warp w computes shift-row bq*4+w.
__global__ void __launch_bounds__(128)
last_ensemble(const float* __restrict__ Hin, const float* __restrict__ W4,
              const float* __restrict__ b4,
              const float* __restrict__ coord, const float* __restrict__ inp,
              float* __restrict__ out)
{
    __shared__ float sp[4][3];
    __shared__ float sa[4];
    int bq = blockIdx.x;
    int warp = threadIdx.x >> 5, lane = threadIdx.x & 31;
    int row = bq*4 + warp;
    const float* hr = Hin + (size_t)row*HID;
    float a0 = 0.f, a1 = 0.f, a2 = 0.f;
    #pragma unroll
    for (int i = 0; i < 8; i++) {
        int k = lane + i*32;
        float h = hr[k];
        a0 += h*W4[k*3 + 0];
        a1 += h*W4[k*3 + 1];
        a2 += h*W4[k*3 + 2];
    }
    #pragma unroll
    for (int o = 16; o; o >>= 1) {
        a0 += __shfl_down_sync(0xffffffffu, a0, o);
        a1 += __shfl_down_sync(0xffffffffu, a1, o);
        a2 += __shfl_down_sync(0xffffffffu, a2, o);
    }
    if (lane == 0) {
        sp[warp][0] = a0 + b4[0];
        sp[warp][1] = a1 + b4[1];
        sp[warp][2] = a2 + b4[2];
        sa[warp] = g_area[row];
    }
    __syncthreads();
    if (threadIdx.x == 0) {
        int b = bq >> 14;
        float cy = coord[(size_t)bq*2 + 0];
        float cx = coord[(size_t)bq*2 + 1];
        float A0 = sa[0], A1 = sa[1], A2 = sa[2], A3 = sa[3];
        float inv = 1.0f/(A0 + A1 + A2 + A3);
        float w0 = A3*inv, w1 = A2*inv, w2 = A1*inv, w3 = A0*inv;
        float fy = fminf(fmaxf((cy + 1.f)*24.f - 0.5f, 0.f), 47.f);
        float fx = fminf(fmaxf((cx + 1.f)*24.f - 0.5f, 0.f), 47.f);
        float y0f = floorf(fy), x0f = floorf(fx);
        int y0 = (int)y0f, x0 = (int)x0f;
        float wy = fy - y0f, wx = fx - x0f;
        int y1 = min(y0 + 1, 47), x1 = min(x0 + 1, 47);
        const float* ib = inp + (size_t)b*3*H0*W0;
        #pragma unroll
        for (int ch = 0; ch < 3; ch++) {
            float r = sp[0][ch]*w0 + sp[1][ch]*w1 + sp[2][ch]*w2 + sp[3][ch]*w3;
            const float* p = ib + ch*H0*W0;
            float v00 = p[y0*48 + x0], v01 = p[y0*48 + x1];
            float v10 = p[y1*48 + x0], v11 = p[y1*48 + x1];
            r += v00*(1.f - wy)*(1.f - wx) + v01*(1.f - wy)*wx
               + v10*wy*(1.f - wx) + v11*wy*wx;
            out[(size_t)bq*3 + ch] = r;
        }
    }
}

// ================= host launch =================
extern "C" void kernel_launch(void* const* d_in, const int* in_sizes, int n_in,
                              void* d_out, int out_size)
{
    const float* inp     = (const float*)d_in[0];
    const float* coord   = (const float*)d_in[1];
    const float* cell    = (const float*)d_in[2];
    const float* enc_w   = (const float*)d_in[3];
    const float* enc_b   = (const float*)d_in[4];
    const float* up1_w   = (const float*)d_in[5];
    const float* up1_b   = (const float*)d_in[6];
    const float* up2_w   = (const float*)d_in[7];
    const float* up2_b   = (const float*)d_in[8];
    const float* up3_w   = (const float*)d_in[9];
    const float* up3_b   = (const float*)d_in[10];
    const float* skip1_w = (const float*)d_in[11];
    const float* skip1_b = (const float*)d_in[12];
    const float* skip2_w = (const float*)d_in[13];
    const float* skip2_b = (const float*)d_in[14];
    const float* down4_w = (const float*)d_in[15];
    const float* down4_b = (const float*)d_in[16];
    const float* down5_w = (const float*)d_in[17];
    const float* down5_b = (const float*)d_in[18];
    const float* mlp_w0  = (const float*)d_in[19];
    const float* mlp_b0  = (const float*)d_in[20];
    const float* mlp_w1  = (const float*)d_in[21];
    const float* mlp_b1  = (const float*)d_in[22];
    const float* mlp_w2  = (const float*)d_in[23];
    const float* mlp_b2  = (const float*)d_in[24];
    const float* mlp_w3  = (const float*)d_in[25];
    const float* mlp_b3  = (const float*)d_in[26];
    const float* mlp_w4  = (const float*)d_in[27];
    const float* mlp_b4  = (const float*)d_in[28];
    float* out = (float*)d_out;

    float *p_feat, *p_feat1, *p_feat2, *p_feat3, *p_feat4, *p_feat5;
    float *p_featL, *p_feat3L, *p_feat4L, *p_feat5L;
    float *p_X, *p_H0, *p_H1, *p_Wt;
    cudaGetSymbolAddress((void**)&p_feat,  g_feat);
    cudaGetSymbolAddress((void**)&p_feat1, g_feat1);
    cudaGetSymbolAddress((void**)&p_feat2, g_feat2);
    cudaGetSymbolAddress((void**)&p_feat3, g_feat3);
    cudaGetSymbolAddress((void**)&p_feat4, g_feat4);
    cudaGetSymbolAddress((void**)&p_feat5, g_feat5);
    cudaGetSymbolAddress((void**)&p_featL,  g_featL);
    cudaGetSymbolAddress((void**)&p_feat3L, g_feat3L);
    cudaGetSymbolAddress((void**)&p_feat4L, g_feat4L);
    cudaGetSymbolAddress((void**)&p_feat5L, g_feat5L);
    cudaGetSymbolAddress((void**)&p_X,  g_X);
    cudaGetSymbolAddress((void**)&p_H0, g_H0b);
    cudaGetSymbolAddress((void**)&p_H1, g_H1b);
    cudaGetSymbolAddress((void**)&p_Wt, g_Wt);

    // weight prep (independent of convs)
    {
        int total = 256*K0P + 3*256*256;
        prep_wt<<<(total + 255)/256, 256>>>(mlp_w0, mlp_w1, mlp_w2, mlp_w3);
    }
    // encoder + pyramid
    {
        int total = BB*CC*H0*W0;
        enc_conv<<<(total + 255)/256, 256>>>(inp, enc_w, enc_b);
        up_conv_ps5<<<dim3(2, 2, BB*64), 128>>>(p_feat,  p_feat1, 48, 48,  up1_w, up1_b);
        up_conv_ps5<<<dim3(3, 3, BB*64), 128>>>(p_feat1, p_feat2, 96, 96,  up2_w, up2_b);
        up_conv_ps5<<<dim3(6, 6, BB*64), 128>>>(p_feat2, p_feat3, 192,192, up3_w, up3_b);
        dim3 blk(16,16);
        down_fused2<<<dim3(12, 12, BB*16), blk>>>(p_feat3, p_feat2, p_feat4, 192, 192,
                                                  down4_w, down4_b, skip1_w, skip1_b);
        down_fused2<<<dim3(6,  6,  BB*16), blk>>>(p_feat4, p_feat1, p_feat5, 96, 96,
                                                  down5_w, down5_b, skip2_w, skip2_b);
    }
    // channel-last transposes for coalesced gather
    {
        dim3 tb(32, 8);
        to_chlast<<<dim3(2304/32,   2, BB), tb>>>(p_feat,  p_featL,  2304);
        to_chlast<<<dim3(9216/32,   2, BB), tb>>>(p_feat5, p_feat5L, 9216);
        to_chlast<<<dim3(36864/32,  2, BB), tb>>>(p_feat4, p_feat4L, 36864);
        to_chlast<<<dim3(147456/32, 2, BB), tb>>>(p_feat3, p_feat3L, 147456);
    }
    // gather + build X (fp32, padded to 272)
    gather_build<<<MROWS/4, 256>>>(coord, cell);

    // MLP hidden layers: scalar-FFMA 128x128 GEMM
    {
        dim3 grid(HID/128, MROWS/128);   // (2, 2048)
        const float* W1 = p_Wt + 256*K0P;
        const float* W2 = W1 + 65536;
        const float* W3 = W2 + 65536;
        gemm_f32<<<grid, 256>>>(p_X,  p_Wt, mlp_b0, p_H0, K0P);
        gemm_f32<<<grid, 256>>>(p_H0, W1,   mlp_b1, p_H1, 256);
        gemm_f32<<<grid, 256>>>(p_H1, W2,   mlp_b2, p_H0, 256);
        gemm_f32<<<grid, 256>>>(p_H0, W3,   mlp_b3, p_H1, 256);
    }
    // fused last layer + ensemble + bilinear skip
    last_ensemble<<<BB*QQ, 128>>>(p_H1, mlp_w4, mlp_b4, coord, inp, out);
}

// round 13
// speedup vs baseline: 2.1690x; 1.1308x over previous
#include <cuda_runtime.h>
#include <cuda_bf16.h>
#include <cstdint>

// ---------------- problem constants ----------------
#define BB     4
#define CC     64
#define H0     48
#define W0     48
#define QQ     16384
#define MROWS  (BB*QQ*4)     // 262144
#define HID    256
#define K0P    272           // layer-0 K (260) padded to multiple of 8

// ---------------- scratch ----------------
__device__ float g_feat [BB*CC*H0*W0];
__device__ float g_feat1[BB*CC*96*96];
__device__ float g_feat2[BB*CC*192*192];
__device__ float g_feat3[BB*CC*384*384];
__device__ float g_feat4[BB*CC*192*192];
__device__ float g_feat5[BB*CC*96*96];
// channel-last copies for coalesced gather
__device__ float g_featL [BB*48*48*CC];
__device__ float g_feat5L[BB*96*96*CC];
__device__ float g_feat4L[BB*192*192*CC];
__device__ float g_feat3L[BB*384*384*CC];
__device__ float g_X  [(size_t)MROWS*K0P];
__device__ float g_H0b[(size_t)MROWS*HID];
__device__ float g_H1b[(size_t)MROWS*HID];
__device__ float g_Wt [256*K0P + 3*256*256];   // transposed weights [n][k]
__device__ float g_area[MROWS];

__device__ __forceinline__ uint32_t smem_u32(const void* p) {
    uint32_t a;
    asm("{ .reg .u64 t; cvta.to.shared.u64 t, %1; cvt.u32.u64 %0, t; }" : "=r"(a) : "l"(p));
    return a;
}

// ================= enc conv (tiny, unchanged) =================
__global__ void enc_conv(const float* __restrict__ inp,
                         const float* __restrict__ w,
                         const float* __restrict__ b)
{
    int idx = blockIdx.x*256 + threadIdx.x;
    if (idx >= BB*CC*H0*W0) return;
    int x  = idx % W0;
    int y  = (idx / W0) % H0;
    int co = (idx / (H0*W0)) % CC;
    int bb = idx / (H0*W0*CC);
    float acc = b[co];
    const float* ib = inp + (size_t)bb*3*H0*W0;
    #pragma unroll
    for (int ci = 0; ci < 3; ci++) {
        #pragma unroll
        for (int ky = 0; ky < 3; ky++) {
            int yy = y + ky - 1;
            if (yy < 0 || yy >= H0) continue;
            #pragma unroll
            for (int kx = 0; kx < 3; kx++) {
                int xx = x + kx - 1;
                if (xx < 0 || xx >= W0) continue;
                acc += ib[ci*H0*W0 + yy*W0 + xx] * w[(co*3 + ci)*9 + ky*3 + kx];
            }
        }
    }
    g_feat[idx] = acc;
}

// ================= up conv 3x3 + pixel shuffle — cp.async 2-stage pipeline =================
// Tile shifted by -4 so global & smem segments are both 16B aligned.
// smem col c <-> global x0-4+c (36 cols). Outputs: [x0-3 .. x0+28].
// Parity layout: [ in(4x34x36) | w(4x4x12) ] per buffer. 2 buffers.
#define PS6_PAR   5088                 // floats per parity (4896 in + 192 w)
#define PS6_WOFF  4896                 // float offset of weight region
#define PS6_NIN   1224                 // input cp tasks (4*34*9)
#define PS6_NTOT  1368                 // + 144 weight tasks

__global__ void __launch_bounds__(128)
up_conv_ps6(const float* __restrict__ in, float* __restrict__ out,
            int H, int W,
            const float* __restrict__ w, const float* __restrict__ bias)
{
    __shared__ float sm[2*PS6_PAR];    // 40704 B
    int tid = threadIdx.x;
    int tx = tid & 7, ty = tid >> 3;
    int x0 = blockIdx.x*32, y0 = blockIdx.y*32;
    int bb = blockIdx.z >> 6;
    int cog = blockIdx.z & 63;
    const float* inb = in + (size_t)bb*CC*H*W;
    const float* wblk = w + (size_t)cog*4*CC*9;
    int bxp = x0 - 3 + tx*4;
    int byp = y0 + ty*2;
    uint32_t sbase = smem_u32(sm);
    int HW = H*W;

    // ---- precompute per-thread cp tasks (chunk-invariant) ----
    int meta[11], gbase[11];
    #pragma unroll
    for (int t = 0; t < 11; t++) {
        int idx = tid + t*128;
        meta[t] = -1; gbase[t] = 0;
        if (idx < PS6_NIN) {
            int seg = idx % 9;
            int rc  = idx / 9;
            int r   = rc % 34;
            int ci  = rc / 34;
            int y   = y0 + r - 1;
            int xg  = x0 - 4 + seg*4;
            bool val = (y >= 0) && (y < H) && (xg >= 0) && (xg <= W - 4);
            int sOff = ((ci*34 + r)*36 + seg*4)*4;
            meta[t]  = sOff | (val ? (1<<17) : 0);
            gbase[t] = val ? (ci*HW + y*W + xg) : 0;
        } else if (idx < PS6_NTOT) {
            int e   = idx - PS6_NIN;      // 0..143
            int col = e / 36;
            int rem = e % 36;
            int ci  = rem / 9;
            int k   = rem % 9;
            int sOff = (PS6_WOFF + (ci*4 + col)*12 + k)*4;
            meta[t]  = sOff | (1<<16);
            gbase[t] = (col*CC + ci)*9 + k;
        }
    }

    auto issue = [&](int chunk, int buf) {
        uint32_t bofs = (uint32_t)buf * (PS6_PAR*4);
        #pragma unroll
        for (int t = 0; t < 11; t++) {
            int m = meta[t];
            if (m < 0) continue;
            uint32_t dst = sbase + bofs + (uint32_t)(m & 0xFFFF);
            if (m & (1<<16)) {
                const float* src = wblk + chunk*36 + gbase[t];
                asm volatile("cp.async.ca.shared.global [%0], [%1], 4;"
                             :: "r"(dst), "l"(src));
            } else {
                int vsz = (m & (1<<17)) ? 16 : 0;
                const float* src = inb + (size_t)chunk*4*HW + gbase[t];
                asm volatile("cp.async.cg.shared.global [%0], [%1], 16, %2;"
                             :: "r"(dst), "l"(src), "r"(vsz));
            }
        }
        asm volatile("cp.async.commit_group;");
    };

    float acc[4][8];
    #pragma unroll
    for (int c = 0; c < 4; c++)
        #pragma unroll
        for (int p = 0; p < 8; p++) acc[c][p] = 0.f;

    issue(0, 0);

    for (int cc = 0; cc < 16; cc++) {
        int buf = cc & 1;
        asm volatile("cp.async.wait_group 0;" ::: "memory");
        __syncthreads();
        if (cc < 15) issue(cc + 1, buf ^ 1);

        const float* sp = sm + buf*PS6_PAR;
        #pragma unroll
        for (int ci = 0; ci < 4; ci++) {
            const float* sr = sp + (ci*34)*36;
            const float* sw = sp + PS6_WOFF + ci*48;
            float v[4][8];
            #pragma unroll
            for (int r = 0; r < 4; r++) {
                float4 p0 = *(const float4*)&sr[(ty*2 + r)*36 + tx*4];
                float4 p1 = *(const float4*)&sr[(ty*2 + r)*36 + tx*4 + 4];
                v[r][0] = p0.x; v[r][1] = p0.y; v[r][2] = p0.z; v[r][3] = p0.w;
                v[r][4] = p1.x; v[r][5] = p1.y; v[r][6] = p1.z; v[r][7] = p1.w;
            }
            #pragma unroll
            for (int col = 0; col < 4; col++) {
                float4 w0 = *(const float4*)&sw[col*12];
                float4 w1 = *(const float4*)&sw[col*12 + 4];
                float4 w2 = *(const float4*)&sw[col*12 + 8];
                float wr[9] = {w0.x, w0.y, w0.z, w0.w, w1.x, w1.y, w1.z, w1.w, w2.x};
                #pragma unroll
                for (int py = 0; py < 2; py++)
                    #pragma unroll
                    for (int px = 0; px < 4; px++) {
                        float a = acc[col][py*4 + px];
                        #pragma unroll
                        for (int ky = 0; ky < 3; ky++)
                            #pragma unroll
                            for (int kx = 0; kx < 3; kx++)
                                a += v[py+ky][px+kx] * wr[ky*3+kx];
                        acc[col][py*4 + px] = a;
                    }
            }
        }
        __syncthreads();
    }

    // ---- epilogue: bias + pixel-shuffle, guarded float2 stores ----
    {
        float b4[4];
        #pragma unroll
        for (int c = 0; c < 4; c++) b4[c] = bias[cog*4 + c];
        int H2 = 2*H, W2 = 2*W;
        float* ob = out + ((size_t)bb*CC + cog)*H2*W2;
        #pragma unroll
        for (int py = 0; py < 2; py++) {
            int yo = byp + py;
            if (yo >= H) continue;
            #pragma unroll
            for (int r2 = 0; r2 < 2; r2++) {
                float* orow = ob + (size_t)(2*yo + r2)*W2;
                #pragma unroll
                for (int p = 0; p < 4; p++) {
                    int ox = bxp + p;
                    if ((unsigned)ox < (unsigned)W) {
                        float2 q;
                        q.x = acc[2*r2+0][py*4+p] + b4[2*r2+0];
                        q.y = acc[2*r2+1][py*4+p] + b4[2*r2+1];
                        *(float2*)(orow + 2*ox) = q;
                    }
                }
            }
        }
    }
}

// ================= stride2 conv3x3 + 1x1 skip (R11, proven) =================
__global__ void down_fused2(const float* __restrict__ in3, const float* __restrict__ skin,
                            float* __restrict__ out, int OH, int OW,
                            const float* __restrict__ dw, const float* __restrict__ db,
                            const float* __restrict__ sw, const float* __restrict__ sb)
{
    __shared__ float s_in[8][33][36];
    __shared__ float s_w[4][8][9];
    __shared__ float s_sw[4][8];
    int IH = 2*OH, IW = 2*OW;
    int tx = threadIdx.x, ty = threadIdx.y, tid = ty*16 + tx;
    int x0 = blockIdx.x*16, y0 = blockIdx.y*16;
    int bb = blockIdx.z >> 4;
    int cog = blockIdx.z & 15;
    float acc[4] = {0.f,0.f,0.f,0.f};
    const float* inb = in3 + (size_t)bb*CC*IH*IW;
    const float* skb = skin + (size_t)bb*CC*OH*OW;
    int oy = y0 + ty, ox = x0 + tx;
    int gx0 = 2*x0;

    for (int c0 = 0; c0 < CC; c0 += 8) {
        __syncthreads();
        for (int idx = tid; idx < 8*33*9; idx += 256) {
            int seg = idx % 9;
            int rc  = idx / 9;
            int r   = rc % 33;
            int ci  = rc / 33;
            int y = 2*y0 - 1 + r;
            bool yok = (y >= 0) && (y < IH);
            const float* grow = inb + (size_t)(c0+ci)*IH*IW + (size_t)y*IW;
            float* srow = &s_in[ci][r][0];
            if (seg < 8) {
                float4 v = make_float4(0.f, 0.f, 0.f, 0.f);
                if (yok) v = *(const float4*)(grow + gx0 + seg*4);
                srow[1 + seg*4 + 0] = v.x;
                srow[1 + seg*4 + 1] = v.y;
                srow[1 + seg*4 + 2] = v.z;
                srow[1 + seg*4 + 3] = v.w;
            } else {
                float lft = 0.f;
                if (yok && gx0 > 0) lft = grow[gx0 - 1];
                srow[0] = lft;
            }
        }
        for (int i = tid; i < 288; i += 256) {
            int col = i / 72, rem = i % 72, ci = rem / 9, k = rem % 9;
            s_w[col][ci][k] = dw[((size_t)(cog*4+col)*CC + c0+ci)*9 + k];
        }
        if (tid < 32) {
            int col = tid >> 3, ci = tid & 7;
            s_sw[col][ci] = sw[(cog*4+col)*CC + c0+ci];
        }
        __syncthreads();
        #pragma unroll
        for (int ci = 0; ci < 8; ci++) {
            float v[9];
            #pragma unroll
            for (int j = 0; j < 9; j++) v[j] = s_in[ci][2*ty + j/3][2*tx + j%3];
            float sv = skb[(size_t)(c0+ci)*OH*OW + oy*OW + ox];
            #pragma unroll
            for (int col = 0; col < 4; col++) {
                float a = acc[col];
                #pragma unroll
                for (int k = 0; k < 9; k++) a += v[k]*s_w[col][ci][k];
                a += sv * s_sw[col][ci];
                acc[col] = a;
            }
        }
    }
    float* ob = out + (size_t)bb*CC*OH*OW;
    #pragma unroll
    for (int col = 0; col < 4; col++) {
        int co = cog*4 + col;
        ob[(size_t)co*OH*OW + oy*OW + ox] = acc[col] + db[co] + sb[co];
    }
}

// ================= channel-last transpose: [b][c][p] -> [b][p][c] =================
__global__ void to_chlast(const float* __restrict__ in, float* __restrict__ out, int P)
{
    __shared__ float t[32][33];
    int p0 = blockIdx.x*32;
    int c0 = blockIdx.y*32;
    int b  = blockIdx.z;
    const float* ib = in + ((size_t)b*CC + c0)*(size_t)P + p0;
    for (int i = threadIdx.y; i < 32; i += 8)
        t[i][threadIdx.x] = ib[(size_t)i*P + threadIdx.x];
    __syncthreads();
    float* ob = out + ((size_t)b*P + p0)*CC + c0;
    for (int i = threadIdx.y; i < 32; i += 8)
        ob[(size_t)i*CC + threadIdx.x] = t[threadIdx.x][i];
}

// ================= weight prep: transpose (fp32) =================
__global__ void prep_wt(const float* __restrict__ w0, const float* __restrict__ w1,
                        const float* __restrict__ w2, const float* __restrict__ w3)
{
    int i = blockIdx.x*256 + threadIdx.x;
    int total = 256*K0P + 3*256*256;
    if (i >= total) return;
    float v;
    if (i < 256*K0P) {
        int n = i / K0P, k = i % K0P;
        v = (k < 260) ? w0[(size_t)k*256 + n] : 0.0f;
    } else {
        int j = i - 256*K0P;
        int l = j / 65536, r = j % 65536;
        int n = r / 256, k = r % 256;
        const float* ws = (l == 0) ? w1 : (l == 1) ? w2 : w3;
        v = ws[(size_t)k*256 + n];
    }
    g_Wt[i] = v;
}

// ================= gather + build X (coalesced channel-last reads) =================
__device__ __forceinline__ int nidx(float cc, float n)
{
    float f = rintf((cc + 1.0f)*(n*0.5f) - 0.5f);
    f = fminf(fmaxf(f, 0.0f), n - 1.0f);
    return (int)f;
}

__global__ void gather_build(const float* __restrict__ coord, const float* __restrict__ cell)
{
    int tid = threadIdx.x;
    int row = blockIdx.x*4 + (tid >> 6);
    int c   = tid & 63;
    int s   = row & 3;
    int bq  = row >> 2;
    int b   = bq >> 14;
    float cy = coord[(size_t)bq*2 + 0];
    float cx = coord[(size_t)bq*2 + 1];
    float vx = (s & 2) ? 1.f : -1.f;
    float vy = (s & 1) ? 1.f : -1.f;
    const float RX = 1.0f/48.0f;
    float sy = fminf(fmaxf(cy + vx*RX + 1e-6f, -1.f + 1e-6f), 1.f - 1e-6f);
    float sx = fminf(fmaxf(cx + vy*RX + 1e-6f, -1.f + 1e-6f), 1.f - 1e-6f);
    int iy0 = nidx(sy, 48.f),  ix0 = nidx(sx, 48.f);
    int iy1 = nidx(sy, 96.f),  ix1 = nidx(sx, 96.f);
    int iy2 = nidx(sy, 192.f), ix2 = nidx(sx, 192.f);
    int iy3 = nidx(sy, 384.f), ix3 = nidx(sx, 384.f);

    float* xr = g_X + (size_t)row*K0P;
    xr[c]       = g_featL [((size_t)b*2304   + iy0*48  + ix0)*CC + c];
    xr[64 + c]  = g_feat5L[((size_t)b*9216   + iy1*96  + ix1)*CC + c];
    xr[128 + c] = g_feat4L[((size_t)b*36864  + iy2*192 + ix2)*CC + c];
    xr[192 + c] = g_feat3L[((size_t)b*147456 + iy3*384 + ix3)*CC + c];
    if (c == 0) {
        float qcy = -1.f + (2.f*iy0 + 1.f)/48.f;
        float qcx = -1.f + (2.f*ix0 + 1.f)/48.f;
        float ry_ = (cy - qcy)*48.f;
        float rx_ = (cx - qcx)*48.f;
        xr[256] = ry_;
        xr[257] = rx_;
        xr[258] = cell[(size_t)bq*2 + 0]*48.f;
        xr[259] = cell[(size_t)bq*2 + 1]*48.f;
        g_area[row] = fabsf(ry_*rx_) + 1e-9f;
    }
    if (c < 12) xr[260 + c] = 0.0f;   // pad to 272
}

// ================= scalar-FFMA SGEMM, 128x128 tile, 8x8/thread =================
__global__ void __launch_bounds__(256)
gemm_f32(const float* __restrict__ A, const float* __restrict__ Wt,
         const float* __restrict__ bias, float* __restrict__ C, int K)
{
    __shared__ float As[2][8][128];
    __shared__ float Bs[2][8][128];
    int tid = threadIdx.x;
    int tx = tid & 15, ty = tid >> 4;
    int m0 = blockIdx.y*128, n0 = blockIdx.x*128;
    int lrow = tid >> 1, lk = (tid & 1)*4;
    const float* ap = A  + (size_t)(m0 + lrow)*K + lk;
    const float* bp = Wt + (size_t)(n0 + lrow)*K + lk;
    int NK = K >> 3;

    float acc[8][8];
    #pragma unroll
    for (int i = 0; i < 8; i++)
        #pragma unroll
        for (int j = 0; j < 8; j++) acc[i][j] = 0.f;

    float4 av = *(const float4*)ap;
    float4 bv = *(const float4*)bp;

    for (int it = 0; it < NK; it++) {
        int buf = it & 1;
        As[buf][lk+0][lrow] = av.x;
        As[buf][lk+1][lrow] = av.y;
        As[buf][lk+2][lrow] = av.z;
        As[buf][lk+3][lrow] = av.w;
        Bs[buf][lk+0][lrow] = bv.x;
        Bs[buf][lk+1][lrow] = bv.y;
        Bs[buf][lk+2][lrow] = bv.z;
        Bs[buf][lk+3][lrow] = bv.w;
        if (it + 1 < NK) {
            av = *(const float4*)(ap + (it+1)*8);
            bv = *(const float4*)(bp + (it+1)*8);
        }
        __syncthreads();
        #pragma unroll
        for (int kk = 0; kk < 8; kk++) {
            float a[8], b[8];
            *(float4*)(a)   = *(const float4*)&As[buf][kk][ty*4];
            *(float4*)(a+4) = *(const float4*)&As[buf][kk][ty*4 + 64];
            *(float4*)(b)   = *(const float4*)&Bs[buf][kk][tx*4];
            *(float4*)(b+4) = *(const float4*)&Bs[buf][kk][tx*4 + 64];
            #pragma unroll
            for (int i = 0; i < 8; i++)
                #pragma unroll
                for (int j = 0; j < 8; j++)
                    acc[i][j] += a[i]*b[j];
        }
    }

    float bn[8];
    #pragma unroll
    for (int j = 0; j < 8; j++)
        bn[j] = bias[n0 + ((j < 4) ? tx*4 + j : 64 + tx*4 + j - 4)];
    #pragma unroll
    for (int i = 0; i < 8; i++) {
        int m = m0 + ((i < 4) ? ty*4 + i : 64 + ty*4 + i - 4);
        float* cr = C + (size_t)m*HID + n0;
        float4 q0 = make_float4(fmaxf(acc[i][0] + bn[0], 0.f),
                                fmaxf(acc[i][1] + bn[1], 0.f),
                                fmaxf(acc[i][2] + bn[2], 0.f),
                                fmaxf(acc[i][3] + bn[3], 0.f));
        float4 q1 = make_float4(fmaxf(acc[i][4] + bn[4], 0.f),
                                fmaxf(acc[i][5] + bn[5], 0.f),
                                fmaxf(acc[i][6] + bn[6], 0.f),
                                fmaxf(acc[i][7] + bn[7], 0.f));
        *(float4*)(cr + tx*4)      = q0;
        *(float4*)(cr + 64 + tx*4) = q1;
    }
}

// ================= fused last layer + ensemble + bilinear skip =================
__global__ void __launch_bounds__(128)
last_ensemble(const float* __restrict__ Hin, const float* __restrict__ W4,
              const float* __restrict__ b4,
              const float* __restrict__ coord, const float* __restrict__ inp,
              float* __restrict__ out)
{
    __shared__ float sp[4][3];
    __shared__ float sa[4];
    int bq = blockIdx.x;
    int warp = threadIdx.x >> 5, lane = threadIdx.x & 31;
    int row = bq*4 + warp;
    const float* hr = Hin + (size_t)row*HID;
    float a0 = 0.f, a1 = 0.f, a2 = 0.f;
    #pragma unroll
    for (int i = 0; i < 8; i++) {
        int k = lane + i*32;
        float h = hr[k];
        a0 += h*W4[k*3 + 0];
        a1 += h*W4[k*3 + 1];
        a2 += h*W4[k*3 + 2];
    }
    #pragma unroll
    for (int o = 16; o; o >>= 1) {
        a0 += __shfl_down_sync(0xffffffffu, a0, o);
        a1 += __shfl_down_sync(0xffffffffu, a1, o);
        a2 += __shfl_down_sync(0xffffffffu, a2, o);
    }
    if (lane == 0) {
        sp[warp][0] = a0 + b4[0];
        sp[warp][1] = a1 + b4[1];
        sp[warp][2] = a2 + b4[2];
        sa[warp] = g_area[row];
    }
    __syncthreads();
    if (threadIdx.x == 0) {
        int b = bq >> 14;
        float cy = coord[(size_t)bq*2 + 0];
        float cx = coord[(size_t)bq*2 + 1];
        float A0 = sa[0], A1 = sa[1], A2 = sa[2], A3 = sa[3];
        float inv = 1.0f/(A0 + A1 + A2 + A3);
        float w0 = A3*inv, w1 = A2*inv, w2 = A1*inv, w3 = A0*inv;
        float fy = fminf(fmaxf((cy + 1.f)*24.f - 0.5f, 0.f), 47.f);
        float fx = fminf(fmaxf((cx + 1.f)*24.f - 0.5f, 0.f), 47.f);
        float y0f = floorf(fy), x0f = floorf(fx);
        int y0 = (int)y0f, x0 = (int)x0f;
        float wy = fy - y0f, wx = fx - x0f;
        int y1 = min(y0 + 1, 47), x1 = min(x0 + 1, 47);
        const float* ib = inp + (size_t)b*3*H0*W0;
        #pragma unroll
        for (int ch = 0; ch < 3; ch++) {
            float r = sp[0][ch]*w0 + sp[1][ch]*w1 + sp[2][ch]*w2 + sp[3][ch]*w3;
            const float* p = ib + ch*H0*W0;
            float v00 = p[y0*48 + x0], v01 = p[y0*48 + x1];
            float v10 = p[y1*48 + x0], v11 = p[y1*48 + x1];
            r += v00*(1.f - wy)*(1.f - wx) + v01*(1.f - wy)*wx
               + v10*wy*(1.f - wx) + v11*wy*wx;
            out[(size_t)bq*3 + ch] = r;
        }
    }
}

// ================= host launch =================
extern "C" void kernel_launch(void* const* d_in, const int* in_sizes, int n_in,
                              void* d_out, int out_size)
{
    const float* inp     = (const float*)d_in[0];
    const float* coord   = (const float*)d_in[1];
    const float* cell    = (const float*)d_in[2];
    const float* enc_w   = (const float*)d_in[3];
    const float* enc_b   = (const float*)d_in[4];
    const float* up1_w   = (const float*)d_in[5];
    const float* up1_b   = (const float*)d_in[6];
    const float* up2_w   = (const float*)d_in[7];
    const float* up2_b   = (const float*)d_in[8];
    const float* up3_w   = (const float*)d_in[9];
    const float* up3_b   = (const float*)d_in[10];
    const float* skip1_w = (const float*)d_in[11];
    const float* skip1_b = (const float*)d_in[12];
    const float* skip2_w = (const float*)d_in[13];
    const float* skip2_b = (const float*)d_in[14];
    const float* down4_w = (const float*)d_in[15];
    const float* down4_b = (const float*)d_in[16];
    const float* down5_w = (const float*)d_in[17];
    const float* down5_b = (const float*)d_in[18];
    const float* mlp_w0  = (const float*)d_in[19];
    const float* mlp_b0  = (const float*)d_in[20];
    const float* mlp_w1  = (const float*)d_in[21];
    const float* mlp_b1  = (const float*)d_in[22];
    const float* mlp_w2  = (const float*)d_in[23];
    const float* mlp_b2  = (const float*)d_in[24];
    const float* mlp_w3  = (const float*)d_in[25];
    const float* mlp_b3  = (const float*)d_in[26];
    const float* mlp_w4  = (const float*)d_in[27];
    const float* mlp_b4  = (const float*)d_in[28];
    float* out = (float*)d_out;

    float *p_feat, *p_feat1, *p_feat2, *p_feat3, *p_feat4, *p_feat5;
    float *p_featL, *p_feat3L, *p_feat4L, *p_feat5L;
    float *p_X, *p_H0, *p_H1, *p_Wt;
    cudaGetSymbolAddress((void**)&p_feat,  g_feat);
    cudaGetSymbolAddress((void**)&p_feat1, g_feat1);
    cudaGetSymbolAddress((void**)&p_feat2, g_feat2);
    cudaGetSymbolAddress((void**)&p_feat3, g_feat3);
    cudaGetSymbolAddress((void**)&p_feat4, g_feat4);
    cudaGetSymbolAddress((void**)&p_feat5, g_feat5);
    cudaGetSymbolAddress((void**)&p_featL,  g_featL);
    cudaGetSymbolAddress((void**)&p_feat3L, g_feat3L);
    cudaGetSymbolAddress((void**)&p_feat4L, g_feat4L);
    cudaGetSymbolAddress((void**)&p_feat5L, g_feat5L);
    cudaGetSymbolAddress((void**)&p_X,  g_X);
    cudaGetSymbolAddress((void**)&p_H0, g_H0b);
    cudaGetSymbolAddress((void**)&p_H1, g_H1b);
    cudaGetSymbolAddress((void**)&p_Wt, g_Wt);

    // weight prep (independent of convs)
    {
        int total = 256*K0P + 3*256*256;
        prep_wt<<<(total + 255)/256, 256>>>(mlp_w0, mlp_w1, mlp_w2, mlp_w3);
    }
    // encoder + pyramid
    {
        int total = BB*CC*H0*W0;
        enc_conv<<<(total + 255)/256, 256>>>(inp, enc_w, enc_b);
        // grid.x covers outputs [32bx-3, 32bx+28]: gx = (W+34)/32
        up_conv_ps6<<<dim3((48+34)/32,  (48+31)/32,  BB*64), 128>>>(p_feat,  p_feat1, 48, 48,  up1_w, up1_b);
        up_conv_ps6<<<dim3((96+34)/32,  (96+31)/32,  BB*64), 128>>>(p_feat1, p_feat2, 96, 96,  up2_w, up2_b);
        up_conv_ps6<<<dim3((192+34)/32, (192+31)/32, BB*64), 128>>>(p_feat2, p_feat3, 192,192, up3_w, up3_b);
        dim3 blk(16,16);
        down_fused2<<<dim3(12, 12, BB*16), blk>>>(p_feat3, p_feat2, p_feat4, 192, 192,
                                                  down4_w, down4_b, skip1_w, skip1_b);
        down_fused2<<<dim3(6,  6,  BB*16), blk>>>(p_feat4, p_feat1, p_feat5, 96, 96,
                                                  down5_w, down5_b, skip2_w, skip2_b);
    }
    // channel-last transposes for coalesced gather
    {
        dim3 tb(32, 8);
        to_chlast<<<dim3(2304/32,   2, BB), tb>>>(p_feat,  p_featL,  2304);
        to_chlast<<<dim3(9216/32,   2, BB), tb>>>(p_feat5, p_feat5L, 9216);
        to_chlast<<<dim3(36864/32,  2, BB), tb>>>(p_feat4, p_feat4L, 36864);
        to_chlast<<<dim3(147456/32, 2, BB), tb>>>(p_feat3, p_feat3L, 147456);
    }
    // gather + build X (fp32, padded to 272)
    gather_build<<<MROWS/4, 256>>>(coord, cell);

    // MLP hidden layers: scalar-FFMA 128x128 GEMM
    {
        dim3 grid(HID/128, MROWS/128);   // (2, 2048)
        const float* W1 = p_Wt + 256*K0P;
        const float* W2 = W1 + 65536;
        const float* W3 = W2 + 65536;
        gemm_f32<<<grid, 256>>>(p_X,  p_Wt, mlp_b0, p_H0, K0P);
        gemm_f32<<<grid, 256>>>(p_H0, W1,   mlp_b1, p_H1, 256);
        gemm_f32<<<grid, 256>>>(p_H1, W2,   mlp_b2, p_H0, 256);
        gemm_f32<<<grid, 256>>>(p_H0, W3,   mlp_b3, p_H1, 256);
    }
    // fused last layer + ensemble + bilinear skip
    last_ensemble<<<BB*QQ, 128>>>(p_H1, mlp_w4, mlp_b4, coord, inp, out);
}

// round 14
// speedup vs baseline: 2.4332x; 1.1218x over previous
#include <cuda_runtime.h>
#include <cuda_bf16.h>
#include <cstdint>

// ---------------- problem constants ----------------
#define BB     4
#define CC     64
#define H0     48
#define W0     48
#define QQ     16384
#define MROWS  (BB*QQ*4)     // 262144
#define HID    256
#define K0P    264           // layer-0 K (260) padded to multiple of 8

// ---------------- scratch ----------------
__device__ float g_feat [BB*CC*H0*W0];
__device__ float g_feat1[BB*CC*96*96];
__device__ float g_feat2[BB*CC*192*192];
__device__ float g_feat3[BB*CC*384*384];
__device__ float g_feat4[BB*CC*192*192];
__device__ float g_feat5[BB*CC*96*96];
// channel-last copies for coalesced gather
__device__ float g_featL [BB*48*48*CC];
__device__ float g_feat5L[BB*96*96*CC];
__device__ float g_feat4L[BB*192*192*CC];
__device__ float g_feat3L[BB*384*384*CC];
__device__ float g_X  [(size_t)MROWS*K0P];
__device__ float g_H0b[(size_t)MROWS*HID];
__device__ float g_H1b[(size_t)MROWS*HID];
__device__ float g_Wt [256*K0P + 3*256*256];   // transposed weights [n][k]
__device__ float g_area[MROWS];

__device__ __forceinline__ uint32_t smem_u32(const void* p) {
    uint32_t a;
    asm("{ .reg .u64 t; cvta.to.shared.u64 t, %1; cvt.u32.u64 %0, t; }" : "=r"(a) : "l"(p));
    return a;
}

// ================= enc conv (tiny, unchanged) =================
__global__ void enc_conv(const float* __restrict__ inp,
                         const float* __restrict__ w,
                         const float* __restrict__ b)
{
    int idx = blockIdx.x*256 + threadIdx.x;
    if (idx >= BB*CC*H0*W0) return;
    int x  = idx % W0;
    int y  = (idx / W0) % H0;
    int co = (idx / (H0*W0)) % CC;
    int bb = idx / (H0*W0*CC);
    float acc = b[co];
    const float* ib = inp + (size_t)bb*3*H0*W0;
    #pragma unroll
    for (int ci = 0; ci < 3; ci++) {
        #pragma unroll
        for (int ky = 0; ky < 3; ky++) {
            int yy = y + ky - 1;
            if (yy < 0 || yy >= H0) continue;
            #pragma unroll
            for (int kx = 0; kx < 3; kx++) {
                int xx = x + kx - 1;
                if (xx < 0 || xx >= W0) continue;
                acc += ib[ci*H0*W0 + yy*W0 + xx] * w[(co*3 + ci)*9 + ky*3 + kx];
            }
        }
    }
    g_feat[idx] = acc;
}

// ================= up conv 3x3 + pixel shuffle — cp.async 2-stage (R13, proven) =================
#define PS6_PAR   5088
#define PS6_WOFF  4896
#define PS6_NIN   1224
#define PS6_NTOT  1368

__global__ void __launch_bounds__(128)
up_conv_ps6(const float* __restrict__ in, float* __restrict__ out,
            int H, int W,
            const float* __restrict__ w, const float* __restrict__ bias)
{
    __shared__ float sm[2*PS6_PAR];
    int tid = threadIdx.x;
    int tx = tid & 7, ty = tid >> 3;
    int x0 = blockIdx.x*32, y0 = blockIdx.y*32;
    int bb = blockIdx.z >> 6;
    int cog = blockIdx.z & 63;
    const float* inb = in + (size_t)bb*CC*H*W;
    const float* wblk = w + (size_t)cog*4*CC*9;
    int bxp = x0 - 3 + tx*4;
    int byp = y0 + ty*2;
    uint32_t sbase = smem_u32(sm);
    int HW = H*W;

    int meta[11], gbase[11];
    #pragma unroll
    for (int t = 0; t < 11; t++) {
        int idx = tid + t*128;
        meta[t] = -1; gbase[t] = 0;
        if (idx < PS6_NIN) {
            int seg = idx % 9;
            int rc  = idx / 9;
            int r   = rc % 34;
            int ci  = rc / 34;
            int y   = y0 + r - 1;
            int xg  = x0 - 4 + seg*4;
            bool val = (y >= 0) && (y < H) && (xg >= 0) && (xg <= W - 4);
            int sOff = ((ci*34 + r)*36 + seg*4)*4;
            meta[t]  = sOff | (val ? (1<<17) : 0);
            gbase[t] = val ? (ci*HW + y*W + xg) : 0;
        } else if (idx < PS6_NTOT) {
            int e   = idx - PS6_NIN;
            int col = e / 36;
            int rem = e % 36;
            int ci  = rem / 9;
            int k   = rem % 9;
            int sOff = (PS6_WOFF + (ci*4 + col)*12 + k)*4;
            meta[t]  = sOff | (1<<16);
            gbase[t] = (col*CC + ci)*9 + k;
        }
    }

    auto issue = [&](int chunk, int buf) {
        uint32_t bofs = (uint32_t)buf * (PS6_PAR*4);
        #pragma unroll
        for (int t = 0; t < 11; t++) {
            int m = meta[t];
            if (m < 0) continue;
            uint32_t dst = sbase + bofs + (uint32_t)(m & 0xFFFF);
            if (m & (1<<16)) {
                const float* src = wblk + chunk*36 + gbase[t];
                asm volatile("cp.async.ca.shared.global [%0], [%1], 4;"
                             :: "r"(dst), "l"(src));
            } else {
                int vsz = (m & (1<<17)) ? 16 : 0;
                const float* src = inb + (size_t)chunk*4*HW + gbase[t];
                asm volatile("cp.async.cg.shared.global [%0], [%1], 16, %2;"
                             :: "r"(dst), "l"(src), "r"(vsz));
            }
        }
        asm volatile("cp.async.commit_group;");
    };

    float acc[4][8];
    #pragma unroll
    for (int c = 0; c < 4; c++)
        #pragma unroll
        for (int p = 0; p < 8; p++) acc[c][p] = 0.f;

    issue(0, 0);

    for (int cc = 0; cc < 16; cc++) {
        int buf = cc & 1;
        asm volatile("cp.async.wait_group 0;" ::: "memory");
        __syncthreads();
        if (cc < 15) issue(cc + 1, buf ^ 1);

        const float* sp = sm + buf*PS6_PAR;
        #pragma unroll
        for (int ci = 0; ci < 4; ci++) {
            const float* sr = sp + (ci*34)*36;
            const float* sw = sp + PS6_WOFF + ci*48;
            float v[4][8];
            #pragma unroll
            for (int r = 0; r < 4; r++) {
                float4 p0 = *(const float4*)&sr[(ty*2 + r)*36 + tx*4];
                float4 p1 = *(const float4*)&sr[(ty*2 + r)*36 + tx*4 + 4];
                v[r][0] = p0.x; v[r][1] = p0.y; v[r][2] = p0.z; v[r][3] = p0.w;
                v[r][4] = p1.x; v[r][5] = p1.y; v[r][6] = p1.z; v[r][7] = p1.w;
            }
            #pragma unroll
            for (int col = 0; col < 4; col++) {
                float4 w0 = *(const float4*)&sw[col*12];
                float4 w1 = *(const float4*)&sw[col*12 + 4];
                float4 w2 = *(const float4*)&sw[col*12 + 8];
                float wr[9] = {w0.x, w0.y, w0.z, w0.w, w1.x, w1.y, w1.z, w1.w, w2.x};
                #pragma unroll
                for (int py = 0; py < 2; py++)
                    #pragma unroll
                    for (int px = 0; px < 4; px++) {
                        float a = acc[col][py*4 + px];
                        #pragma unroll
                        for (int ky = 0; ky < 3; ky++)
                            #pragma unroll
                            for (int kx = 0; kx < 3; kx++)
                                a += v[py+ky][px+kx] * wr[ky*3+kx];
                        acc[col][py*4 + px] = a;
                    }
            }
        }
        __syncthreads();
    }

    {
        float b4[4];
        #pragma unroll
        for (int c = 0; c < 4; c++) b4[c] = bias[cog*4 + c];
        int H2 = 2*H, W2 = 2*W;
        float* ob = out + ((size_t)bb*CC + cog)*H2*W2;
        #pragma unroll
        for (int py = 0; py < 2; py++) {
            int yo = byp + py;
            if (yo >= H) continue;
            #pragma unroll
            for (int r2 = 0; r2 < 2; r2++) {
                float* orow = ob + (size_t)(2*yo + r2)*W2;
                #pragma unroll
                for (int p = 0; p < 4; p++) {
                    int ox = bxp + p;
                    if ((unsigned)ox < (unsigned)W) {
                        float2 q;
                        q.x = acc[2*r2+0][py*4+p] + b4[2*r2+0];
                        q.y = acc[2*r2+1][py*4+p] + b4[2*r2+1];
                        *(float2*)(orow + 2*ox) = q;
                    }
                }
            }
        }
    }
}

// ================= stride2 conv3x3 + 1x1 skip — cp.async 2-stage pipeline =================
// 4-channel chunks. smem col c <-> global gx0-4+c (36 cols); compute reads col 3+2tx+kx.
// Parity: [ in(4x33x36)=4752 | dw(4x4x12)=192 | sw(16) ] = 4960 floats; 2 buffers = 39.7KB.
#define DN_PAR    4960
#define DN_WOFF   4752
#define DN_SWOFF  4944
#define DN_NIN    1188                 // 4ci*33row*9seg
#define DN_NW     (DN_NIN + 144)       // + dw tasks
#define DN_NTOT   (DN_NW + 16)         // + sw tasks

__global__ void __launch_bounds__(256)
down_fused3(const float* __restrict__ in3, const float* __restrict__ skin,
            float* __restrict__ out, int OH, int OW,
            const float* __restrict__ dw, const float* __restrict__ db,
            const float* __restrict__ sw, const float* __restrict__ sb)
{
    __shared__ float sm[2*DN_PAR];
    int IH = 2*OH, IW = 2*OW;
    int tid = threadIdx.x;
    int tx = tid & 15, ty = tid >> 4;
    int x0 = blockIdx.x*16, y0 = blockIdx.y*16;
    int bb = blockIdx.z >> 4;
    int cog = blockIdx.z & 15;
    const float* inb = in3 + (size_t)bb*CC*IH*IW;
    const float* skb = skin + (size_t)bb*CC*OH*OW;
    const float* dwb = dw + (size_t)cog*4*CC*9;
    const float* swb = sw + (size_t)cog*4*CC;
    int oy = y0 + ty, ox = x0 + tx;
    int gx0 = 2*x0;
    uint32_t sbase = smem_u32(sm);
    int IHW = IH*IW;

    // task tables: type in bits[16:18): 0=input16B, 1=dw4B, 2=sw4B; bit18 = input-valid
    int meta[6], gofs[6];
    #pragma unroll
    for (int t = 0; t < 6; t++) {
        int idx = tid + t*256;
        meta[t] = -1; gofs[t] = 0;
        if (idx < DN_NIN) {
            int seg = idx % 9;
            int rc  = idx / 9;
            int r   = rc % 33;
            int ci  = rc / 33;
            int y   = 2*y0 - 1 + r;
            int xg  = gx0 - 4 + seg*4;
            bool val = (y >= 0) && (y < IH) && (xg >= 0);
            int sOff = ((ci*33 + r)*36 + seg*4)*4;
            meta[t]  = sOff | (val ? (1<<18) : 0);
            gofs[t]  = val ? (ci*IHW + y*IW + xg) : 0;
        } else if (idx < DN_NW) {
            int e   = idx - DN_NIN;       // 0..143
            int ci  = e / 36;
            int rem = e % 36;
            int col = rem / 9;
            int k   = rem % 9;
            int sOff = (DN_WOFF + (ci*4 + col)*12 + k)*4;
            meta[t]  = sOff | (1<<16);
            gofs[t]  = (col*CC + ci)*9 + k;
        } else if (idx < DN_NTOT) {
            int e   = idx - DN_NW;        // 0..15, e = ci*4+col
            int ci  = e >> 2, col = e & 3;
            int sOff = (DN_SWOFF + e)*4;
            meta[t]  = sOff | (2<<16);
            gofs[t]  = col*CC + ci;
        }
    }

    auto issue = [&](int chunk, int buf) {
        uint32_t bofs = (uint32_t)buf * (DN_PAR*4);
        #pragma unroll
        for (int t = 0; t < 6; t++) {
            int m = meta[t];
            if (m < 0) continue;
            uint32_t dst = sbase + bofs + (uint32_t)(m & 0xFFFF);
            int type = (m >> 16) & 3;
            if (type == 0) {
                int vsz = (m & (1<<18)) ? 16 : 0;
                const float* src = inb + (size_t)chunk*4*IHW + gofs[t];
                asm volatile("cp.async.cg.shared.global [%0], [%1], 16, %2;"
                             :: "r"(dst), "l"(src), "r"(vsz));
            } else if (type == 1) {
                const float* src = dwb + chunk*36 + gofs[t];
                asm volatile("cp.async.ca.shared.global [%0], [%1], 4;"
                             :: "r"(dst), "l"(src));
            } else {
                const float* src = swb + chunk*4 + gofs[t];
                asm volatile("cp.async.ca.shared.global [%0], [%1], 4;"
                             :: "r"(dst), "l"(src));
            }
        }
        asm volatile("cp.async.commit_group;");
    };

    float acc[4] = {0.f, 0.f, 0.f, 0.f};
    issue(0, 0);

    for (int cc = 0; cc < 16; cc++) {
        int buf = cc & 1;
        asm volatile("cp.async.wait_group 0;" ::: "memory");
        __syncthreads();
        if (cc < 15) issue(cc + 1, buf ^ 1);

        const float* sp = sm + buf*DN_PAR;
        int c0 = cc*4;
        #pragma unroll
        for (int ci = 0; ci < 4; ci++) {
            const float* sr = sp + (ci*33)*36;
            float v[9];
            #pragma unroll
            for (int j = 0; j < 9; j++)
                v[j] = sr[(2*ty + j/3)*36 + 3 + 2*tx + j%3];
            float sv = skb[(size_t)(c0+ci)*OH*OW + oy*OW + ox];
            #pragma unroll
            for (int col = 0; col < 4; col++) {
                const float* wp = sp + DN_WOFF + (ci*4 + col)*12;
                float a = acc[col];
                #pragma unroll
                for (int k = 0; k < 9; k++) a += v[k]*wp[k];
                a += sv * sp[DN_SWOFF + ci*4 + col];
                acc[col] = a;
            }
        }
        __syncthreads();
    }

    float* ob = out + (size_t)bb*CC*OH*OW;
    #pragma unroll
    for (int col = 0; col < 4; col++) {
        int co = cog*4 + col;
        ob[(size_t)co*OH*OW + oy*OW + ox] = acc[col] + db[co] + sb[co];
    }
}

// ================= channel-last transpose: [b][c][p] -> [b][p][c] =================
__global__ void to_chlast(const float* __restrict__ in, float* __restrict__ out, int P)
{
    __shared__ float t[32][33];
    int p0 = blockIdx.x*32;
    int c0 = blockIdx.y*32;
    int b  = blockIdx.z;
    const float* ib = in + ((size_t)b*CC + c0)*(size_t)P + p0;
    for (int i = threadIdx.y; i < 32; i += 8)
        t[i][threadIdx.x] = ib[(size_t)i*P + threadIdx.x];
    __syncthreads();
    float* ob = out + ((size_t)b*P + p0)*CC + c0;
    for (int i = threadIdx.y; i < 32; i += 8)
        ob[(size_t)i*CC + threadIdx.x] = t[threadIdx.x][i];
}

// ================= weight prep: transpose (fp32) =================
__global__ void prep_wt(const float* __restrict__ w0, const float* __restrict__ w1,
                        const float* __restrict__ w2, const float* __restrict__ w3)
{
    int i = blockIdx.x*256 + threadIdx.x;
    int total = 256*K0P + 3*256*256;
    if (i >= total) return;
    float v;
    if (i < 256*K0P) {
        int n = i / K0P, k = i % K0P;
        v = (k < 260) ? w0[(size_t)k*256 + n] : 0.0f;
    } else {
        int j = i - 256*K0P;
        int l = j / 65536, r = j % 65536;
        int n = r / 256, k = r % 256;
        const float* ws = (l == 0) ? w1 : (l == 1) ? w2 : w3;
        v = ws[(size_t)k*256 + n];
    }
    g_Wt[i] = v;
}

// ================= gather + build X (coalesced channel-last reads) =================
__device__ __forceinline__ int nidx(float cc, float n)
{
    float f = rintf((cc + 1.0f)*(n*0.5f) - 0.5f);
    f = fminf(fmaxf(f, 0.0f), n - 1.0f);
    return (int)f;
}

__global__ void gather_build(const float* __restrict__ coord, const float* __restrict__ cell)
{
    int tid = threadIdx.x;
    int row = blockIdx.x*4 + (tid >> 6);
    int c   = tid & 63;
    int s   = row & 3;
    int bq  = row >> 2;
    int b   = bq >> 14;
    float cy = coord[(size_t)bq*2 + 0];
    float cx = coord[(size_t)bq*2 + 1];
    float vx = (s & 2) ? 1.f : -1.f;
    float vy = (s & 1) ? 1.f : -1.f;
    const float RX = 1.0f/48.0f;
    float sy = fminf(fmaxf(cy + vx*RX + 1e-6f, -1.f + 1e-6f), 1.f - 1e-6f);
    float sx = fminf(fmaxf(cx + vy*RX + 1e-6f, -1.f + 1e-6f), 1.f - 1e-6f);
    int iy0 = nidx(sy, 48.f),  ix0 = nidx(sx, 48.f);
    int iy1 = nidx(sy, 96.f),  ix1 = nidx(sx, 96.f);
    int iy2 = nidx(sy, 192.f), ix2 = nidx(sx, 192.f);
    int iy3 = nidx(sy, 384.f), ix3 = nidx(sx, 384.f);

    float* xr = g_X + (size_t)row*K0P;
    xr[c]       = g_featL [((size_t)b*2304   + iy0*48  + ix0)*CC + c];
    xr[64 + c]  = g_feat5L[((size_t)b*9216   + iy1*96  + ix1)*CC + c];
    xr[128 + c] = g_feat4L[((size_t)b*36864  + iy2*192 + ix2)*CC + c];
    xr[192 + c] = g_feat3L[((size_t)b*147456 + iy3*384 + ix3)*CC + c];
    if (c == 0) {
        float qcy = -1.f + (2.f*iy0 + 1.f)/48.f;
        float qcx = -1.f + (2.f*ix0 + 1.f)/48.f;
        float ry_ = (cy - qcy)*48.f;
        float rx_ = (cx - qcx)*48.f;
        xr[256] = ry_;
        xr[257] = rx_;
        xr[258] = cell[(size_t)bq*2 + 0]*48.f;
        xr[259] = cell[(size_t)bq*2 + 1]*48.f;
        g_area[row] = fabsf(ry_*rx_) + 1e-9f;
    }
    if (c < 4) xr[260 + c] = 0.0f;   // pad to 264
}

// ================= scalar-FFMA SGEMM, 128x128 tile, 8x8/thread =================
__global__ void __launch_bounds__(256)
gemm_f32(const float* __restrict__ A, const float* __restrict__ Wt,
         const float* __restrict__ bias, float* __restrict__ C, int K)
{
    __shared__ float As[2][8][128];
    __shared__ float Bs[2][8][128];
    int tid = threadIdx.x;
    int tx = tid & 15, ty = tid >> 4;
    int m0 = blockIdx.y*128, n0 = blockIdx.x*128;
    int lrow = tid >> 1, lk = (tid & 1)*4;
    const float* ap = A  + (size_t)(m0 + lrow)*K + lk;
    const float* bp = Wt + (size_t)(n0 + lrow)*K + lk;
    int NK = K >> 3;

    float acc[8][8];
    #pragma unroll
    for (int i = 0; i < 8; i++)
        #pragma unroll
        for (int j = 0; j < 8; j++) acc[i][j] = 0.f;

    float4 av = *(const float4*)ap;
    float4 bv = *(const float4*)bp;

    for (int it = 0; it < NK; it++) {
        int buf = it & 1;
        As[buf][lk+0][lrow] = av.x;
        As[buf][lk+1][lrow] = av.y;
        As[buf][lk+2][lrow] = av.z;
        As[buf][lk+3][lrow] = av.w;
        Bs[buf][lk+0][lrow] = bv.x;
        Bs[buf][lk+1][lrow] = bv.y;
        Bs[buf][lk+2][lrow] = bv.z;
        Bs[buf][lk+3][lrow] = bv.w;
        if (it + 1 < NK) {
            av = *(const float4*)(ap + (it+1)*8);
            bv = *(const float4*)(bp + (it+1)*8);
        }
        __syncthreads();
        #pragma unroll
        for (int kk = 0; kk < 8; kk++) {
            float a[8], b[8];
            *(float4*)(a)   = *(const float4*)&As[buf][kk][ty*4];
            *(float4*)(a+4) = *(const float4*)&As[buf][kk][ty*4 + 64];
            *(float4*)(b)   = *(const float4*)&Bs[buf][kk][tx*4];
            *(float4*)(b+4) = *(const float4*)&Bs[buf][kk][tx*4 + 64];
            #pragma unroll
            for (int i = 0; i < 8; i++)
                #pragma unroll
                for (int j = 0; j < 8; j++)
                    acc[i][j] += a[i]*b[j];
        }
    }

    float bn[8];
    #pragma unroll
    for (int j = 0; j < 8; j++)
        bn[j] = bias[n0 + ((j < 4) ? tx*4 + j : 64 + tx*4 + j - 4)];
    #pragma unroll
    for (int i = 0; i < 8; i++) {
        int m = m0 + ((i < 4) ? ty*4 + i : 64 + ty*4 + i - 4);
        float* cr = C + (size_t)m*HID + n0;
        float4 q0 = make_float4(fmaxf(acc[i][0] + bn[0], 0.f),
                                fmaxf(acc[i][1] + bn[1], 0.f),
                                fmaxf(acc[i][2] + bn[2], 0.f),
                                fmaxf(acc[i][3] + bn[3], 0.f));
        float4 q1 = make_float4(fmaxf(acc[i][4] + bn[4], 0.f),
                                fmaxf(acc[i][5] + bn[5], 0.f),
                                fmaxf(acc[i][6] + bn[6], 0.f),
                                fmaxf(acc[i][7] + bn[7], 0.f));
        *(float4*)(cr + tx*4)      = q0;
        *(float4*)(cr + 64 + tx*4) = q1;
    }
}

// ================= fused last layer + ensemble + bilinear skip =================
__global__ void __launch_bounds__(128)
last_ensemble(const float* __restrict__ Hin, const float* __restrict__ W4,
              const float* __restrict__ b4,
              const float* __restrict__ coord, const float* __restrict__ inp,
              float* __restrict__ out)
{
    __shared__ float sp[4][3];
    __shared__ float sa[4];
    int bq = blockIdx.x;
    int warp = threadIdx.x >> 5, lane = threadIdx.x & 31;
    int row = bq*4 + warp;
    const float* hr = Hin + (size_t)row*HID;
    float a0 = 0.f, a1 = 0.f, a2 = 0.f;
    #pragma unroll
    for (int i = 0; i < 8; i++) {
        int k = lane + i*32;
        float h = hr[k];
        a0 += h*W4[k*3 + 0];
        a1 += h*W4[k*3 + 1];
        a2 += h*W4[k*3 + 2];
    }
    #pragma unroll
    for (int o = 16; o; o >>= 1) {
        a0 += __shfl_down_sync(0xffffffffu, a0, o);
        a1 += __shfl_down_sync(0xffffffffu, a1, o);
        a2 += __shfl_down_sync(0xffffffffu, a2, o);
    }
    if (lane == 0) {
        sp[warp][0] = a0 + b4[0];
        sp[warp][1] = a1 + b4[1];
        sp[warp][2] = a2 + b4[2];
        sa[warp] = g_area[row];
    }
    __syncthreads();
    if (threadIdx.x == 0) {
        int b = bq >> 14;
        float cy = coord[(size_t)bq*2 + 0];
        float cx = coord[(size_t)bq*2 + 1];
        float A0 = sa[0], A1 = sa[1], A2 = sa[2], A3 = sa[3];
        float inv = 1.0f/(A0 + A1 + A2 + A3);
        float w0 = A3*inv, w1 = A2*inv, w2 = A1*inv, w3 = A0*inv;
        float fy = fminf(fmaxf((cy + 1.f)*24.f - 0.5f, 0.f), 47.f);
        float fx = fminf(fmaxf((cx + 1.f)*24.f - 0.5f, 0.f), 47.f);
        float y0f = floorf(fy), x0f = floorf(fx);
        int y0 = (int)y0f, x0 = (int)x0f;
        float wy = fy - y0f, wx = fx - x0f;
        int y1 = min(y0 + 1, 47), x1 = min(x0 + 1, 47);
        const float* ib = inp + (size_t)b*3*H0*W0;
        #pragma unroll
        for (int ch = 0; ch < 3; ch++) {
            float r = sp[0][ch]*w0 + sp[1][ch]*w1 + sp[2][ch]*w2 + sp[3][ch]*w3;
            const float* p = ib + ch*H0*W0;
            float v00 = p[y0*48 + x0], v01 = p[y0*48 + x1];
            float v10 = p[y1*48 + x0], v11 = p[y1*48 + x1];
            r += v00*(1.f - wy)*(1.f - wx) + v01*(1.f - wy)*wx
               + v10*wy*(1.f - wx) + v11*wy*wx;
            out[(size_t)bq*3 + ch] = r;
        }
    }
}

// ================= host launch =================
extern "C" void kernel_launch(void* const* d_in, const int* in_sizes, int n_in,
                              void* d_out, int out_size)
{
    const float* inp     = (const float*)d_in[0];
    const float* coord   = (const float*)d_in[1];
    const float* cell    = (const float*)d_in[2];
    const float* enc_w   = (const float*)d_in[3];
    const float* enc_b   = (const float*)d_in[4];
    const float* up1_w   = (const float*)d_in[5];
    const float* up1_b   = (const float*)d_in[6];
    const float* up2_w   = (const float*)d_in[7];
    const float* up2_b   = (const float*)d_in[8];
    const float* up3_w   = (const float*)d_in[9];
    const float* up3_b   = (const float*)d_in[10];
    const float* skip1_w = (const float*)d_in[11];
    const float* skip1_b = (const float*)d_in[12];
    const float* skip2_w = (const float*)d_in[13];
    const float* skip2_b = (const float*)d_in[14];
    const float* down4_w = (const float*)d_in[15];
    const float* down4_b = (const float*)d_in[16];
    const float* down5_w = (const float*)d_in[17];
    const float* down5_b = (const float*)d_in[18];
    const float* mlp_w0  = (const float*)d_in[19];
    const float* mlp_b0  = (const float*)d_in[20];
    const float* mlp_w1  = (const float*)d_in[21];
    const float* mlp_b1  = (const float*)d_in[22];
    const float* mlp_w2  = (const float*)d_in[23];
    const float* mlp_b2  = (const float*)d_in[24];
    const float* mlp_w3  = (const float*)d_in[25];
    const float* mlp_b3  = (const float*)d_in[26];
    const float* mlp_w4  = (const float*)d_in[27];
    const float* mlp_b4  = (const float*)d_in[28];
    float* out = (float*)d_out;

    float *p_feat, *p_feat1, *p_feat2, *p_feat3, *p_feat4, *p_feat5;
    float *p_featL, *p_feat3L, *p_feat4L, *p_feat5L;
    float *p_X, *p_H0, *p_H1, *p_Wt;
    cudaGetSymbolAddress((void**)&p_feat,  g_feat);
    cudaGetSymbolAddress((void**)&p_feat1, g_feat1);
    cudaGetSymbolAddress((void**)&p_feat2, g_feat2);
    cudaGetSymbolAddress((void**)&p_feat3, g_feat3);
    cudaGetSymbolAddress((void**)&p_feat4, g_feat4);
    cudaGetSymbolAddress((void**)&p_feat5, g_feat5);
    cudaGetSymbolAddress((void**)&p_featL,  g_featL);
    cudaGetSymbolAddress((void**)&p_feat3L, g_feat3L);
    cudaGetSymbolAddress((void**)&p_feat4L, g_feat4L);
    cudaGetSymbolAddress((void**)&p_feat5L, g_feat5L);
    cudaGetSymbolAddress((void**)&p_X,  g_X);
    cudaGetSymbolAddress((void**)&p_H0, g_H0b);
    cudaGetSymbolAddress((void**)&p_H1, g_H1b);
    cudaGetSymbolAddress((void**)&p_Wt, g_Wt);

    // weight prep (independent of convs)
    {
        int total = 256*K0P + 3*256*256;
        prep_wt<<<(total + 255)/256, 256>>>(mlp_w0, mlp_w1, mlp_w2, mlp_w3);
    }
    // encoder + pyramid
    {
        int total = BB*CC*H0*W0;
        enc_conv<<<(total + 255)/256, 256>>>(inp, enc_w, enc_b);
        up_conv_ps6<<<dim3((48+34)/32,  (48+31)/32,  BB*64), 128>>>(p_feat,  p_feat1, 48, 48,  up1_w, up1_b);
        up_conv_ps6<<<dim3((96+34)/32,  (96+31)/32,  BB*64), 128>>>(p_feat1, p_feat2, 96, 96,  up2_w, up2_b);
        up_conv_ps6<<<dim3((192+34)/32, (192+31)/32, BB*64), 128>>>(p_feat2, p_feat3, 192,192, up3_w, up3_b);
        down_fused3<<<dim3(12, 12, BB*16), 256>>>(p_feat3, p_feat2, p_feat4, 192, 192,
                                                  down4_w, down4_b, skip1_w, skip1_b);
        down_fused3<<<dim3(6,  6,  BB*16), 256>>>(p_feat4, p_feat1, p_feat5, 96, 96,
                                                  down5_w, down5_b, skip2_w, skip2_b);
    }
    // channel-last transposes for coalesced gather
    {
        dim3 tb(32, 8);
        to_chlast<<<dim3(2304/32,   2, BB), tb>>>(p_feat,  p_featL,  2304);
        to_chlast<<<dim3(9216/32,   2, BB), tb>>>(p_feat5, p_feat5L, 9216);
        to_chlast<<<dim3(36864/32,  2, BB), tb>>>(p_feat4, p_feat4L, 36864);
        to_chlast<<<dim3(147456/32, 2, BB), tb>>>(p_feat3, p_feat3L, 147456);
    }
    // gather + build X (fp32, padded to 264)
    gather_build<<<MROWS/4, 256>>>(coord, cell);

    // MLP hidden layers: scalar-FFMA 128x128 GEMM
    {
        dim3 grid(HID/128, MROWS/128);   // (2, 2048)
        const float* W1 = p_Wt + 256*K0P;
        const float* W2 = W1 + 65536;
        const float* W3 = W2 + 65536;
        gemm_f32<<<grid, 256>>>(p_X,  p_Wt, mlp_b0, p_H0, K0P);
        gemm_f32<<<grid, 256>>>(p_H0, W1,   mlp_b1, p_H1, 256);
        gemm_f32<<<grid, 256>>>(p_H1, W2,   mlp_b2, p_H0, 256);
        gemm_f32<<<grid, 256>>>(p_H0, W3,   mlp_b3, p_H1, 256);
    }
    // fused last layer + ensemble + bilinear skip
    last_ensemble<<<BB*QQ, 128>>>(p_H1, mlp_w4, mlp_b4, coord, inp, out);
}